// round 15
// baseline (speedup 1.0000x reference)
#include <cuda_runtime.h>
#include <cuda_bf16.h>
#include <cuda_fp16.h>

typedef unsigned long long ull;

// B=32, S=64, D=256, H=8, E=8, topk=2, F=1024, LATENT=64, HD=32
#define TOK      2048
#define DMODEL   256
#define NBIG     16384
#define FEXP     1024
#define NEXP     8
#define WLSPLIT  4
#define WLKC     (NBIG/WLSPLIT)   // 4096

// ---------------- scratch ----------------
__device__ float  g_y1 [TOK*DMODEL];
__device__ float  g_part[WLSPLIT*32*NBIG];
__device__ float  g_lat[TOK*DMODEL];
__device__ float  g_qkv[3*TOK*DMODEL];
__device__ float  g_ao [TOK*DMODEL];
__device__ float  g_x2 [TOK*DMODEL];
__device__ float  g_y2 [TOK*DMODEL];
__device__ float  g_topv[TOK*2];
__device__ int    g_cnt[NEXP];
__device__ int    g_list[NEXP*TOK];
__device__ float  g_h1 [NEXP*TOK*FEXP];
__device__ float  g_h2 [NEXP*TOK*FEXP];
__device__ float  g_eo [2*TOK*DMODEL];
__device__ __align__(16) __half g_w116[NEXP*DMODEL*FEXP];
__device__ __align__(16) __half g_ws16[NEXP*FEXP*FEXP];
__device__ __align__(16) __half g_w216[NEXP*FEXP*DMODEL];
__device__ __align__(16) __half g_wq16[DMODEL*DMODEL];
__device__ __align__(16) __half g_wk16[DMODEL*DMODEL];
__device__ __align__(16) __half g_wv16[DMODEL*DMODEL];
__device__ __align__(16) __half g_wo16[DMODEL*DMODEL];

// ---------------- helpers ----------------
__device__ __forceinline__ unsigned smem_u32(const void* p) {
    return (unsigned)__cvta_generic_to_shared(p);
}
#define CPA16(dst, src) asm volatile("cp.async.cg.shared.global [%0], [%1], 16;" :: "r"(dst), "l"(src))
#define CPA_COMMIT()    asm volatile("cp.async.commit_group;")
#define CPA_WAIT0()     asm volatile("cp.async.wait_group 0;")
#define CPA_WAIT1()     asm volatile("cp.async.wait_group 1;")
__device__ __forceinline__ void ldm_x4(unsigned* r, unsigned addr) {
    asm volatile("ldmatrix.sync.aligned.m8n8.x4.shared.b16 {%0,%1,%2,%3}, [%4];"
        : "=r"(r[0]), "=r"(r[1]), "=r"(r[2]), "=r"(r[3]) : "r"(addr));
}
__device__ __forceinline__ void ldm_x4t(unsigned* r, unsigned addr) {
    asm volatile("ldmatrix.sync.aligned.m8n8.x4.trans.shared.b16 {%0,%1,%2,%3}, [%4];"
        : "=r"(r[0]), "=r"(r[1]), "=r"(r[2]), "=r"(r[3]) : "r"(addr));
}
__device__ __forceinline__ void ldm_x2t(unsigned* r, unsigned addr) {
    asm volatile("ldmatrix.sync.aligned.m8n8.x2.trans.shared.b16 {%0,%1}, [%2];"
        : "=r"(r[0]), "=r"(r[1]) : "r"(addr));
}
__device__ __forceinline__ void mma_f16(float* c, const unsigned* a, const unsigned* b) {
    asm volatile("mma.sync.aligned.m16n8k16.row.col.f32.f16.f16.f32 "
        "{%0,%1,%2,%3}, {%4,%5,%6,%7}, {%8,%9}, {%0,%1,%2,%3};"
        : "+f"(c[0]), "+f"(c[1]), "+f"(c[2]), "+f"(c[3])
        : "r"(a[0]), "r"(a[1]), "r"(a[2]), "r"(a[3]), "r"(b[0]), "r"(b[1]));
}
// fp16 pack (round-to-nearest)
__device__ __forceinline__ unsigned pack_f16(float x, float y) {
    unsigned r;
    asm("cvt.rn.f16x2.f32 %0, %1, %2;" : "=r"(r) : "f"(y), "f"(x));
    return r;
}
// fp16 exact 2-term split of a pair
__device__ __forceinline__ void split_pair_f16(float x, float y, unsigned& hi, unsigned& lo) {
    hi = pack_f16(x, y);
    __half2 h = *reinterpret_cast<__half2*>(&hi);
    float2 hf = __half22float2(h);
    lo = pack_f16(x - hf.x, y - hf.y);
}

// ================= hgemm: BM=128 BN=128 BK=32, fp32 A (2-pass split) + fp16 W ====
// mode 0: C[r]=A[r]@W+bias(+resid)   mode 1: A gathered via list>>1 -> C at e*TOK
// mode 2: A at e*TOK -> C at e*TOK (+relu)   mode 3: A at e*TOK -> C scattered
// mode 5: dual launch: z selects {A,W,bias}; C slice z*TOK*N (used for K/V)
#define A128_STRIDE 40      // f16 elems (80 B)
#define B128_STRIDE 136     // f16 elems (272 B)
#define AH128 0
#define AL128 10240
#define BH128 20480
#define BUF128 29184        // AH + AL + BH(8704)
#define ROWP128 (2*BUF128)
#define SMEM128 (2*BUF128 + 1024 + 256)

extern "C" __global__ void __launch_bounds__(256, 2)
hgemm(const float* __restrict__ A, const __half* __restrict__ W16,
      const float* __restrict__ bias, const float* __restrict__ resid,
      float* __restrict__ C, int M, int N, int K, int lda,
      const int* __restrict__ list, const int* __restrict__ cntp,
      int mode, int relu,
      const float* A2, const __half* Wk16, const __half* Wv16,
      const float* bk2, const float* bv3) {
    extern __shared__ char sm_raw[];
    char* sm = (char*)(((ull)sm_raw + 127) & ~127ULL);

    int z = blockIdx.z;
    int e = (mode >= 1 && mode <= 3) ? z : 0;
    const float* Asrc = A;
    const __half* Wsrc = W16;
    const float* bsrc = bias;
    if (mode == 5 && z > 0) {
        Asrc = A2;
        Wsrc = (z == 1) ? Wk16 : Wv16;
        bsrc = (z == 1) ? bk2 : bv3;
    }
    int rows = cntp ? cntp[e] : M;
    int m0 = blockIdx.y * 128;
    if (m0 >= rows) return;
    int n0 = blockIdx.x * 128;
    int tid = threadIdx.x;
    int lane = tid & 31, w = tid >> 5;
    int wm = w & 1, wn = w >> 1;

    const __half* We = Wsrc + (size_t)e * K * N;
    const float* be = bsrc + (size_t)e * N;

    const float** rowp = (const float**)(sm + ROWP128);
    if (tid < 128) {
        int r = m0 + tid;
        const float* p = nullptr;
        if (r < rows) {
            if (mode == 1)      p = Asrc + (size_t)(list[e*TOK + r] >> 1) * lda;
            else if (mode == 2 || mode == 3) p = Asrc + ((size_t)e*TOK + r) * lda;
            else                p = Asrc + (size_t)r * lda;
        }
        rowp[tid] = p;
    }
    __syncthreads();

    unsigned smbase = smem_u32(sm);
    int aq = lane >> 3, ar = lane & 7;
    unsigned a_base = smbase + AH128 +
        (unsigned)(((wm*64 + ar + 8*(aq & 1)) * A128_STRIDE + 8*(aq >> 1)) * 2);
    int bt = lane >> 3;
    int bkrow = (bt & 1)*8 + (lane & 7);
    int bnoff = (bt >> 1)*8;
    unsigned b_base = smbase + BH128 +
        (unsigned)((bkrow * B128_STRIDE + wn*32 + bnoff) * 2);

    float acc[4][4][4];
    #pragma unroll
    for (int i = 0; i < 4; i++)
        #pragma unroll
        for (int j = 0; j < 4; j++)
            #pragma unroll
            for (int q = 0; q < 4; q++) acc[i][j][q] = 0.f;

    int nch = K >> 5;
    float4 av[4];

    // ---- prologue: chunk 0 ----
    {
        unsigned bb = smbase;
        #pragma unroll
        for (int p = 0; p < 2; p++) {
            int s = tid + 256*p;
            CPA16(bb + BH128 + (s >> 4)*272 + (s & 15)*16,
                  (const char*)(We + (size_t)(s >> 4)*N + n0 + (s & 15)*8));
        }
        CPA_COMMIT();
        #pragma unroll
        for (int p = 0; p < 4; p++) {
            int s = tid + 256*p;
            const float* rp = rowp[s >> 3];
            av[p] = rp ? *(const float4*)(rp + (s & 7)*4) : make_float4(0.f,0.f,0.f,0.f);
        }
        char* bc = sm;
        #pragma unroll
        for (int p = 0; p < 4; p++) {
            int s = tid + 256*p;
            int m = s >> 3, kq = s & 7;
            unsigned h0, l0, h1, l1;
            split_pair_f16(av[p].x, av[p].y, h0, l0);
            split_pair_f16(av[p].z, av[p].w, h1, l1);
            unsigned aoff = (unsigned)(m*(A128_STRIDE*2) + kq*8);
            *(uint2*)(bc + AH128 + aoff) = make_uint2(h0, h1);
            *(uint2*)(bc + AL128 + aoff) = make_uint2(l0, l1);
        }
        CPA_WAIT0();
        __syncthreads();
    }

    for (int c = 0; c < nch; c++) {
        int buf = c & 1;
        bool has = (c + 1 < nch);
        if (has) {
            int kc = (c + 1) << 5;
            unsigned bb = smbase + (unsigned)((buf ^ 1) * BUF128);
            #pragma unroll
            for (int p = 0; p < 2; p++) {
                int s = tid + 256*p;
                CPA16(bb + BH128 + (s >> 4)*272 + (s & 15)*16,
                      (const char*)(We + (size_t)(kc + (s >> 4))*N + n0 + (s & 15)*8));
            }
            CPA_COMMIT();
            #pragma unroll
            for (int p = 0; p < 4; p++) {
                int s = tid + 256*p;
                const float* rp = rowp[s >> 3];
                av[p] = rp ? *(const float4*)(rp + kc + (s & 7)*4) : make_float4(0.f,0.f,0.f,0.f);
            }
        }
        // ---- compute on buf ----
        unsigned bufo = (unsigned)(buf * BUF128);
        #pragma unroll
        for (int ks = 0; ks < 2; ks++) {
            unsigned ah[4][4], al[4][4], bf[2][4];
            unsigned ab = a_base + bufo + ks*32;
            unsigned bb2 = b_base + bufo + ks*16*(B128_STRIDE*2);
            #pragma unroll
            for (int i = 0; i < 4; i++) {
                ldm_x4(ah[i], ab + i*16*(A128_STRIDE*2));
                ldm_x4(al[i], ab + i*16*(A128_STRIDE*2) + (AL128 - AH128));
            }
            #pragma unroll
            for (int jj = 0; jj < 2; jj++) ldm_x4t(bf[jj], bb2 + jj*32);
            #pragma unroll
            for (int i = 0; i < 4; i++)
                #pragma unroll
                for (int j = 0; j < 4; j++) {
                    mma_f16(acc[i][j], ah[i], &bf[j >> 1][(j & 1)*2]);
                    mma_f16(acc[i][j], al[i], &bf[j >> 1][(j & 1)*2]);
                }
        }
        if (has) {
            char* bc = sm + (buf ^ 1) * BUF128;
            #pragma unroll
            for (int p = 0; p < 4; p++) {
                int s = tid + 256*p;
                int m = s >> 3, kq = s & 7;
                unsigned h0, l0, h1, l1;
                split_pair_f16(av[p].x, av[p].y, h0, l0);
                split_pair_f16(av[p].z, av[p].w, h1, l1);
                unsigned aoff = (unsigned)(m*(A128_STRIDE*2) + kq*8);
                *(uint2*)(bc + AH128 + aoff) = make_uint2(h0, h1);
                *(uint2*)(bc + AL128 + aoff) = make_uint2(l0, l1);
            }
            CPA_WAIT0();
        }
        __syncthreads();
    }

    // ---- epilogue ----
    #pragma unroll
    for (int i = 0; i < 4; i++) {
        int r0 = m0 + wm*64 + 16*i + (lane >> 2);
        #pragma unroll
        for (int hf = 0; hf < 2; hf++) {
            int row = r0 + hf*8;
            if (row >= rows) continue;
            float* crow;
            const float* rsd = nullptr;
            if (mode == 3) {
                int ent = list[e*TOK + row];
                crow = C + (size_t)(ent & 1)*TOK*N + (size_t)(ent >> 1)*N;
            } else if (mode == 0) {
                crow = C + (size_t)row * N;
                if (resid) rsd = resid + (size_t)row * N;
            } else if (mode == 5) {
                crow = C + (size_t)z*TOK*N + (size_t)row * N;
            } else {      // mode 1 / 2
                crow = C + ((size_t)e*TOK + row) * N;
            }
            #pragma unroll
            for (int j = 0; j < 4; j++) {
                int col = n0 + wn*32 + 8*j + 2*(lane & 3);
                float v0 = acc[i][j][hf*2 + 0];
                float v1 = acc[i][j][hf*2 + 1];
                v0 += be[col]; v1 += be[col + 1];
                if (rsd) { v0 += rsd[col]; v1 += rsd[col + 1]; }
                if (relu) { v0 = fmaxf(v0, 0.f); v1 = fmaxf(v1, 0.f); }
                *(float2*)(crow + col) = make_float2(v0, v1);
            }
        }
    }
}

// ================= hgemm_wl: BM=32 BN=256 BK=32, split-K=4, fp16 2-pass ==========
// B pipelined depth-2 via cp.async of RAW fp32 into smem staging, then converted
// smem->smem into the fp16 buffer. A via 1-deep register prefetch (tiny).
#define AW_STRIDE 40
#define BW_STRIDE 264
#define AHW 0
#define ALW 2560
#define BHW 5120
#define BUF16W 22016                 // A hi/lo + B fp16
#define STG32A (2*BUF16W)            // 44032: fp32 staging slot 0 (32 KB)
#define STG32B (STG32A + 32768)      // 76800: fp32 staging slot 1
#define SMEMW (STG32B + 32768 + 128) // 109696

extern "C" __global__ void __launch_bounds__(256)
hgemm_wl(const float* __restrict__ A, const float* __restrict__ W,
         float* __restrict__ part) {
    extern __shared__ char sm_raw[];
    char* sm = (char*)(((ull)sm_raw + 127) & ~127ULL);

    int n0 = blockIdx.x * 256;
    int z  = blockIdx.y;
    int tid = threadIdx.x;
    int lane = tid & 31, w = tid >> 5;

    const float* Ab = A + (size_t)z * WLKC;
    const float* Wb = W + (size_t)z * WLKC * NBIG;

    unsigned smbase = smem_u32(sm);
    int aq = lane >> 3, ar = lane & 7;
    unsigned a_base = smbase + AHW +
        (unsigned)(((ar + 8*(aq & 1)) * AW_STRIDE + 8*(aq >> 1)) * 2);
    unsigned b_base = smbase + BHW +
        (unsigned)(((lane & 15) * BW_STRIDE + w*32) * 2);

    float acc[2][4][4];
    #pragma unroll
    for (int i = 0; i < 2; i++)
        #pragma unroll
        for (int j = 0; j < 4; j++)
            #pragma unroll
            for (int q = 0; q < 4; q++) acc[i][j][q] = 0.f;

    const int nch = WLKC >> 5;   // 128
    int am = tid >> 3, akq = tid & 7;

    // ---- issue B chunk c (raw fp32) into staging slot c&1 ----
    #define WL_ISSUE_B(c_) do { \
        unsigned dst = smbase + (((c_) & 1) ? STG32B : STG32A); \
        int kc_ = (c_) << 5; \
        _Pragma("unroll") \
        for (int p = 0; p < 8; p++) { \
            int g = tid + 256*p; \
            CPA16(dst + (unsigned)g*16, \
                  (const char*)(Wb + (size_t)(kc_ + (g >> 6))*NBIG + n0 + (g & 63)*4)); \
        } \
        CPA_COMMIT(); \
    } while (0)

    // ---- convert B chunk c from staging to fp16 buffer c&1 ----
    #define WL_CONV_B(c_) do { \
        const float4* src = (const float4*)(sm + (((c_) & 1) ? STG32B : STG32A)); \
        char* bb = sm + ((c_) & 1) * BUF16W; \
        _Pragma("unroll") \
        for (int p = 0; p < 8; p++) { \
            int g = tid + 256*p; \
            float4 v = src[g]; \
            unsigned bh0 = pack_f16(v.x, v.y); \
            unsigned bh1 = pack_f16(v.z, v.w); \
            int kk = g >> 6, n4 = g & 63; \
            *(uint2*)(bb + BHW + kk*(BW_STRIDE*2) + n4*8) = make_uint2(bh0, bh1); \
        } \
    } while (0)

    // ---- A: load+split+store chunk c into fp16 buffer c&1 ----
    #define WL_STAGE_A(c_) do { \
        int kc_ = (c_) << 5; \
        float4 av = *(const float4*)(Ab + (size_t)am*NBIG + kc_ + akq*4); \
        unsigned h0, l0, h1, l1; \
        split_pair_f16(av.x, av.y, h0, l0); \
        split_pair_f16(av.z, av.w, h1, l1); \
        char* bb = sm + ((c_) & 1) * BUF16W; \
        unsigned aoff = (unsigned)(am*(AW_STRIDE*2) + akq*8); \
        *(uint2*)(bb + AHW + aoff) = make_uint2(h0, h1); \
        *(uint2*)(bb + ALW + aoff) = make_uint2(l0, l1); \
    } while (0)

    // ---- prologue ----
    WL_ISSUE_B(0);
    WL_ISSUE_B(1);
    WL_STAGE_A(0);
    CPA_WAIT1();            // chunk 0 staged (chunk 1 still in flight)
    WL_CONV_B(0);
    __syncthreads();

    for (int c = 0; c < nch; c++) {
        int buf = c & 1;
        bool has = (c + 1 < nch);
        if (c + 2 < nch) WL_ISSUE_B(c + 2);   // reuses staging slot c&1 (already converted)

        // ---- compute on buf ----
        unsigned bufo = (unsigned)(buf * BUF16W);
        #pragma unroll
        for (int ks = 0; ks < 2; ks++) {
            unsigned ah[2][4], al[2][4], bh[4][2];
            unsigned ab = a_base + bufo + ks*32;
            unsigned bb2 = b_base + bufo + ks*16*(BW_STRIDE*2);
            #pragma unroll
            for (int i = 0; i < 2; i++) {
                ldm_x4(ah[i], ab + i*16*(AW_STRIDE*2));
                ldm_x4(al[i], ab + i*16*(AW_STRIDE*2) + (ALW - AHW));
            }
            #pragma unroll
            for (int j = 0; j < 4; j++) ldm_x2t(bh[j], bb2 + j*16);
            #pragma unroll
            for (int i = 0; i < 2; i++)
                #pragma unroll
                for (int j = 0; j < 4; j++) {
                    mma_f16(acc[i][j], ah[i], bh[j]);
                    mma_f16(acc[i][j], al[i], bh[j]);
                }
        }

        if (has) {
            WL_STAGE_A(c + 1);
            if (c + 2 < nch) CPA_WAIT1(); else CPA_WAIT0();
            WL_CONV_B(c + 1);
        }
        __syncthreads();
    }

    float* pz = part + (size_t)z * 32 * NBIG;
    #pragma unroll
    for (int i = 0; i < 2; i++) {
        int r0 = 16*i + (lane >> 2);
        #pragma unroll
        for (int hf = 0; hf < 2; hf++) {
            int row = r0 + hf*8;
            float* crow = pz + (size_t)row * NBIG;
            #pragma unroll
            for (int j = 0; j < 4; j++) {
                int col = n0 + w*32 + 8*j + 2*(lane & 3);
                *(float2*)(crow + col) =
                    make_float2(acc[i][j][hf*2 + 0], acc[i][j][hf*2 + 1]);
            }
        }
    }
    #undef WL_ISSUE_B
    #undef WL_CONV_B
    #undef WL_STAGE_A
}

// ---------------- weight conversion (vectorized) ----------------
__global__ void cvt_moe_w(const float* __restrict__ W1, const float* __restrict__ Ws,
                          const float* __restrict__ W2, __half* __restrict__ o1,
                          __half* __restrict__ os, __half* __restrict__ o2) {
    size_t i = ((size_t)blockIdx.x * 256 + threadIdx.x) * 4;
    const size_t n1 = (size_t)NEXP*DMODEL*FEXP;
    const size_t ns = (size_t)NEXP*FEXP*FEXP;
    const float* s; __half* d; size_t j;
    if (i < n1)            { s = W1; d = o1; j = i; }
    else if (i < n1 + ns)  { s = Ws; d = os; j = i - n1; }
    else                   { s = W2; d = o2; j = i - n1 - ns; }
    float4 v = *(const float4*)(s + j);
    *(__half2*)(d + j)     = __floats2half2_rn(v.x, v.y);
    *(__half2*)(d + j + 2) = __floats2half2_rn(v.z, v.w);
}
__global__ void cvt_qkvo_w(const float* __restrict__ Wq, const float* __restrict__ Wk,
                           const float* __restrict__ Wv, const float* __restrict__ Wo,
                           __half* __restrict__ oq, __half* __restrict__ ok,
                           __half* __restrict__ ov, __half* __restrict__ oo) {
    size_t i = ((size_t)blockIdx.x * 256 + threadIdx.x) * 4;
    int seg = (int)(i >> 16);
    size_t j = i & 65535;
    const float* s = (seg == 0) ? Wq : (seg == 1) ? Wk : (seg == 2) ? Wv : Wo;
    __half* d = (seg == 0) ? oq : (seg == 1) ? ok : (seg == 2) ? ov : oo;
    float4 v = *(const float4*)(s + j);
    *(__half2*)(d + j)     = __floats2half2_rn(v.x, v.y);
    *(__half2*)(d + j + 2) = __floats2half2_rn(v.z, v.w);
}

// ---------------- rmsnorm: 1 warp per row, 8 rows/block ----------------
__global__ void rmsnorm_kernel(const float* __restrict__ in, const float* __restrict__ w,
                               float* __restrict__ out) {
    int row = blockIdx.x * 8 + (threadIdx.x >> 5);
    int lane = threadIdx.x & 31;
    const float* ip = in + (size_t)row * DMODEL;
    float4 v0 = *(const float4*)(ip + lane*4);
    float4 v1 = *(const float4*)(ip + 128 + lane*4);
    float ss = v0.x*v0.x + v0.y*v0.y + v0.z*v0.z + v0.w*v0.w
             + v1.x*v1.x + v1.y*v1.y + v1.z*v1.z + v1.w*v1.w;
    #pragma unroll
    for (int o = 16; o > 0; o >>= 1) ss += __shfl_xor_sync(0xffffffffu, ss, o);
    float sc = rsqrtf(ss * (1.0f/256.0f) + 1e-5f);
    float4 w0 = *(const float4*)(w + lane*4);
    float4 w1 = *(const float4*)(w + 128 + lane*4);
    float* op = out + (size_t)row * DMODEL;
    *(float4*)(op + lane*4) =
        make_float4(v0.x*sc*w0.x, v0.y*sc*w0.y, v0.z*sc*w0.z, v0.w*sc*w0.w);
    *(float4*)(op + 128 + lane*4) =
        make_float4(v1.x*sc*w1.x, v1.y*sc*w1.y, v1.z*sc*w1.z, v1.w*sc*w1.w);
}

// ---------------- Wl split-K reduce ----------------
__global__ void wl_reduce(const float* __restrict__ part, const float* __restrict__ bl,
                          float* __restrict__ lat) {
    int i = blockIdx.x * 256 + threadIdx.x;
    float s = bl[i & (NBIG-1)];
    #pragma unroll
    for (int p = 0; p < WLSPLIT; p++) s += part[(size_t)p*32*NBIG + i];
    lat[i] = s;
}

// ---------------- attention ----------------
__global__ void attn_kernel(const float* __restrict__ q, const float* __restrict__ k,
                            const float* __restrict__ v, float* __restrict__ ao) {
    int bh = blockIdx.x;
    int b = bh >> 3, h = bh & 7;
    int s = threadIdx.x;
    __shared__ float ks[64][32];
    __shared__ float vs[64][32];
    for (int idx = s; idx < 2048; idx += 64) {
        int l = idx >> 5, d = idx & 31;
        size_t src = (size_t)(b*64 + l)*DMODEL + h*32 + d;
        ks[l][d] = k[src];
        vs[l][d] = v[src];
    }
    __syncthreads();

    float qr[32];
    const float* qp = q + (size_t)(b*64 + s)*DMODEL + h*32;
    #pragma unroll
    for (int d = 0; d < 32; d++) qr[d] = qp[d];

    // RoPE (bug-faithful: imaginary part uses the updated real part)
    #pragma unroll
    for (int i = 0; i < 16; i++) {
        float fr = powf(10000.0f, -(float)i / 16.0f);
        float ang = (float)s * fr;
        float c = cosf(ang), sn = sinf(ang);
        float X = qr[2*i], Y = qr[2*i + 1];
        float nX = X*c - Y*sn;
        float nY = nX*sn + Y*c;
        qr[2*i] = nX; qr[2*i + 1] = nY;
    }

    const float scale = 0.1767766952966369f;
    float sc[64];
    float mx = -1e30f;
    #pragma unroll
    for (int l = 0; l < 64; l++) {
        float p = 0.f;
        #pragma unroll
        for (int d = 0; d < 32; d++) p += qr[d] * ks[l][d];
        p *= scale;
        sc[l] = p;
        mx = fmaxf(mx, p);
    }
    float se = 0.f;
    #pragma unroll
    for (int l = 0; l < 64; l++) { sc[l] = __expf(sc[l] - mx); se += sc[l]; }
    float inv = 1.0f / se;

    float* op = ao + (size_t)(b*64 + s)*DMODEL + h*32;
    #pragma unroll
    for (int d = 0; d < 32; d++) {
        float a = 0.f;
        #pragma unroll
        for (int l = 0; l < 64; l++) a += sc[l] * vs[l][d];
        op[d] = a * inv;
    }
}

// ---------------- router ----------------
__global__ void zero_cnt_kernel(int* cnt) { if (threadIdx.x < NEXP) cnt[threadIdx.x] = 0; }

__global__ void route_kernel(const float* __restrict__ y2, const float* __restrict__ rw,
                             const float* __restrict__ rb, float* __restrict__ topv,
                             int* __restrict__ cnt, int* __restrict__ list) {
    int tok = blockIdx.x, lane = threadIdx.x;
    float xv[8];
    #pragma unroll
    for (int j = 0; j < 8; j++) xv[j] = y2[(size_t)tok*DMODEL + j*32 + lane];
    float lg[8];
    #pragma unroll
    for (int e = 0; e < 8; e++) {
        float p = 0.f;
        #pragma unroll
        for (int j = 0; j < 8; j++) p += xv[j] * rw[(j*32 + lane)*NEXP + e];
        #pragma unroll
        for (int o = 16; o > 0; o >>= 1) p += __shfl_xor_sync(0xffffffffu, p, o);
        lg[e] = p;
    }
    if (lane == 0) {
        float mx = -1e30f;
        #pragma unroll
        for (int e = 0; e < 8; e++) { lg[e] += rb[e]; mx = fmaxf(mx, lg[e]); }
        float se = 0.f, pr[8];
        #pragma unroll
        for (int e = 0; e < 8; e++) { pr[e] = __expf(lg[e] - mx); se += pr[e]; }
        float inv = 1.0f / se;
        #pragma unroll
        for (int e = 0; e < 8; e++) pr[e] *= inv;
        int b0 = 0; float v0 = -1.f;
        #pragma unroll
        for (int e = 0; e < 8; e++) if (pr[e] > v0) { v0 = pr[e]; b0 = e; }
        int b1 = -1; float v1 = -1.f;
        #pragma unroll
        for (int e = 0; e < 8; e++) if (e != b0 && pr[e] > v1) { v1 = pr[e]; b1 = e; }
        topv[tok*2 + 0] = v0;
        topv[tok*2 + 1] = v1;
        int p0 = atomicAdd(&cnt[b0], 1); list[b0*TOK + p0] = tok*2;
        int p1 = atomicAdd(&cnt[b1], 1); list[b1*TOK + p1] = tok*2 + 1;
    }
}

// ---------------- combine ----------------
__global__ void combine_kernel(const float* __restrict__ x2, const float* __restrict__ topv,
                               const float* __restrict__ eo, float* __restrict__ out) {
    int tok = blockIdx.x, d = threadIdx.x;
    size_t i = (size_t)tok*DMODEL + d;
    out[i] = x2[i] + topv[tok*2] * eo[i] + topv[tok*2 + 1] * eo[(size_t)TOK*DMODEL + i];
}

// ---------------- host ----------------
extern "C" void kernel_launch(void* const* d_in, const int* in_sizes, int n_in,
                              void* d_out, int out_size) {
    const float* x   = (const float*)d_in[0];
    const float* r1w = (const float*)d_in[1];
    const float* Wl  = (const float*)d_in[2];
    const float* bl  = (const float*)d_in[3];
    const float* Wq  = (const float*)d_in[4];
    const float* bq  = (const float*)d_in[5];
    const float* Wk  = (const float*)d_in[6];
    const float* bk  = (const float*)d_in[7];
    const float* Wv  = (const float*)d_in[8];
    const float* bv  = (const float*)d_in[9];
    const float* Wo  = (const float*)d_in[10];
    const float* bo  = (const float*)d_in[11];
    const float* r2w = (const float*)d_in[12];
    const float* rw  = (const float*)d_in[13];
    const float* rb  = (const float*)d_in[14];
    const float* W1  = (const float*)d_in[15];
    const float* b1  = (const float*)d_in[16];
    const float* Wsx = (const float*)d_in[17];
    const float* bs  = (const float*)d_in[18];
    const float* W2  = (const float*)d_in[19];
    const float* b2  = (const float*)d_in[20];

    float *y1, *part, *lat, *qkv, *ao, *x2, *y2, *topv, *h1, *h2, *eo;
    __half *w116, *ws16, *w216, *wq16, *wk16, *wv16, *wo16;
    int *cnt, *list;
    cudaGetSymbolAddress((void**)&y1,   g_y1);
    cudaGetSymbolAddress((void**)&part, g_part);
    cudaGetSymbolAddress((void**)&lat,  g_lat);
    cudaGetSymbolAddress((void**)&qkv,  g_qkv);
    cudaGetSymbolAddress((void**)&ao,   g_ao);
    cudaGetSymbolAddress((void**)&x2,   g_x2);
    cudaGetSymbolAddress((void**)&y2,   g_y2);
    cudaGetSymbolAddress((void**)&topv, g_topv);
    cudaGetSymbolAddress((void**)&cnt,  g_cnt);
    cudaGetSymbolAddress((void**)&list, g_list);
    cudaGetSymbolAddress((void**)&h1,   g_h1);
    cudaGetSymbolAddress((void**)&h2,   g_h2);
    cudaGetSymbolAddress((void**)&eo,   g_eo);
    cudaGetSymbolAddress((void**)&w116, g_w116);
    cudaGetSymbolAddress((void**)&ws16, g_ws16);
    cudaGetSymbolAddress((void**)&w216, g_w216);
    cudaGetSymbolAddress((void**)&wq16, g_wq16);
    cudaGetSymbolAddress((void**)&wk16, g_wk16);
    cudaGetSymbolAddress((void**)&wv16, g_wv16);
    cudaGetSymbolAddress((void**)&wo16, g_wo16);

    static int inited = 0;
    static cudaStream_t s1, s2;
    static cudaEvent_t evFork, evCvt, evRms1, evQ;
    if (!inited) {
        cudaFuncSetAttribute(hgemm,    cudaFuncAttributeMaxDynamicSharedMemorySize, SMEM128);
        cudaFuncSetAttribute(hgemm_wl, cudaFuncAttributeMaxDynamicSharedMemorySize, SMEMW);
        cudaStreamCreateWithFlags(&s1, cudaStreamNonBlocking);
        cudaStreamCreateWithFlags(&s2, cudaStreamNonBlocking);
        cudaEventCreateWithFlags(&evFork, cudaEventDisableTiming);
        cudaEventCreateWithFlags(&evCvt,  cudaEventDisableTiming);
        cudaEventCreateWithFlags(&evRms1, cudaEventDisableTiming);
        cudaEventCreateWithFlags(&evQ,    cudaEventDisableTiming);
        inited = 1;
    }

    // ---- side stream s1: weight cvt + cnt zero (off critical path) ----
    cudaEventRecord(evFork, 0);
    cudaStreamWaitEvent(s1, evFork, 0);
    cvt_qkvo_w<<<256, 256, 0, s1>>>(Wq, Wk, Wv, Wo, wq16, wk16, wv16, wo16);
    cvt_moe_w<<<12288, 256, 0, s1>>>(W1, Wsx, W2, w116, ws16, w216);
    zero_cnt_kernel<<<1, 32, 0, s1>>>(cnt);
    cudaEventRecord(evCvt, s1);

    // ---- main chain ----
    rmsnorm_kernel<<<TOK/8, 256>>>(x, r1w, y1);
    cudaEventRecord(evRms1, 0);

    // ---- s2: Q projection overlapping Wl ----
    cudaStreamWaitEvent(s2, evRms1, 0);
    cudaStreamWaitEvent(s2, evCvt, 0);
    hgemm<<<dim3(2, 16, 1), 256, SMEM128, s2>>>(y1, wq16, bq, nullptr, qkv,
        TOK, DMODEL, DMODEL, DMODEL, nullptr, nullptr, 0, 0,
        nullptr, nullptr, nullptr, nullptr, nullptr);
    cudaEventRecord(evQ, s2);

    hgemm_wl<<<dim3(64, WLSPLIT), 256, SMEMW>>>(y1, Wl, part);
    wl_reduce<<<TOK, 256>>>(part, bl, lat);

    // K/V: mode 5, z=0 -> K(lat,wk16,bk) slice 1, z=1 -> V(lat,wv16,bv) slice 2
    cudaStreamWaitEvent(0, evCvt, 0);
    hgemm<<<dim3(2, 16, 2), 256, SMEM128>>>(lat, wk16, bk, nullptr, qkv + (size_t)TOK*DMODEL,
        TOK, DMODEL, DMODEL, DMODEL, nullptr, nullptr, 5, 0,
        lat, wv16, wv16, bv, bv);

    cudaStreamWaitEvent(0, evQ, 0);
    attn_kernel<<<256, 64>>>(qkv, qkv + (size_t)TOK*DMODEL, qkv + 2*(size_t)TOK*DMODEL, ao);
    hgemm<<<dim3(2, 16, 1), 256, SMEM128>>>(ao, wo16, bo, x, x2,
        TOK, DMODEL, DMODEL, DMODEL, nullptr, nullptr, 0, 0,
        nullptr, nullptr, nullptr, nullptr, nullptr);

    // --- MoE ---
    rmsnorm_kernel<<<TOK/8, 256>>>(x2, r2w, y2);
    route_kernel<<<TOK, 32>>>(y2, rw, rb, topv, cnt, list);
    hgemm<<<dim3(8, 16, NEXP), 256, SMEM128>>>(y2, w116, b1, nullptr, h1,
        0, FEXP, DMODEL, DMODEL, list, cnt, 1, 0,
        nullptr, nullptr, nullptr, nullptr, nullptr);
    hgemm<<<dim3(8, 16, NEXP), 256, SMEM128>>>(h1, ws16, bs, nullptr, h2,
        0, FEXP, FEXP, FEXP, list, cnt, 2, 1,
        nullptr, nullptr, nullptr, nullptr, nullptr);
    hgemm<<<dim3(2, 16, NEXP), 256, SMEM128>>>(h2, w216, b2, nullptr, eo,
        0, DMODEL, FEXP, FEXP, list, cnt, 3, 0,
        nullptr, nullptr, nullptr, nullptr, nullptr);
    combine_kernel<<<TOK, 256>>>(x2, topv, eo, (float*)d_out);
}

// round 16
// speedup vs baseline: 1.3492x; 1.3492x over previous
#include <cuda_runtime.h>
#include <cuda_bf16.h>
#include <cuda_fp16.h>

typedef unsigned long long ull;

// B=32, S=64, D=256, H=8, E=8, topk=2, F=1024, LATENT=64, HD=32
#define TOK      2048
#define DMODEL   256
#define NBIG     16384
#define FEXP     1024
#define NEXP     8
#define WLSPLIT  4
#define WLKC     (NBIG/WLSPLIT)   // 4096

// ---------------- scratch ----------------
__device__ float  g_y1 [TOK*DMODEL];
__device__ float  g_part[WLSPLIT*32*NBIG];
__device__ float  g_lat[TOK*DMODEL];
__device__ float  g_qkv[3*TOK*DMODEL];
__device__ float  g_ao [TOK*DMODEL];
__device__ float  g_x2 [TOK*DMODEL];
__device__ float  g_y2 [TOK*DMODEL];
__device__ float  g_topv[TOK*2];
__device__ int    g_cnt[NEXP];
__device__ int    g_list[NEXP*TOK];
__device__ float  g_eo [2*TOK*DMODEL];
__device__ __align__(16) __half g_h1x[NEXP*TOK*FEXP];
__device__ __align__(16) __half g_h2x[NEXP*TOK*FEXP];
__device__ __align__(16) __half g_w116[NEXP*DMODEL*FEXP];
__device__ __align__(16) __half g_ws16[NEXP*FEXP*FEXP];
__device__ __align__(16) __half g_w216[NEXP*FEXP*DMODEL];
__device__ __align__(16) __half g_wq16[DMODEL*DMODEL];
__device__ __align__(16) __half g_wk16[DMODEL*DMODEL];
__device__ __align__(16) __half g_wv16[DMODEL*DMODEL];
__device__ __align__(16) __half g_wo16[DMODEL*DMODEL];

// ---------------- helpers ----------------
__device__ __forceinline__ unsigned smem_u32(const void* p) {
    return (unsigned)__cvta_generic_to_shared(p);
}
#define CPA16(dst, src) asm volatile("cp.async.cg.shared.global [%0], [%1], 16;" :: "r"(dst), "l"(src))
#define CPA_COMMIT()    asm volatile("cp.async.commit_group;")
#define CPA_WAIT0()     asm volatile("cp.async.wait_group 0;")
__device__ __forceinline__ void ldm_x4(unsigned* r, unsigned addr) {
    asm volatile("ldmatrix.sync.aligned.m8n8.x4.shared.b16 {%0,%1,%2,%3}, [%4];"
        : "=r"(r[0]), "=r"(r[1]), "=r"(r[2]), "=r"(r[3]) : "r"(addr));
}
__device__ __forceinline__ void ldm_x4t(unsigned* r, unsigned addr) {
    asm volatile("ldmatrix.sync.aligned.m8n8.x4.trans.shared.b16 {%0,%1,%2,%3}, [%4];"
        : "=r"(r[0]), "=r"(r[1]), "=r"(r[2]), "=r"(r[3]) : "r"(addr));
}
__device__ __forceinline__ void ldm_x2t(unsigned* r, unsigned addr) {
    asm volatile("ldmatrix.sync.aligned.m8n8.x2.trans.shared.b16 {%0,%1}, [%2];"
        : "=r"(r[0]), "=r"(r[1]) : "r"(addr));
}
__device__ __forceinline__ void mma_f16(float* c, const unsigned* a, const unsigned* b) {
    asm volatile("mma.sync.aligned.m16n8k16.row.col.f32.f16.f16.f32 "
        "{%0,%1,%2,%3}, {%4,%5,%6,%7}, {%8,%9}, {%0,%1,%2,%3};"
        : "+f"(c[0]), "+f"(c[1]), "+f"(c[2]), "+f"(c[3])
        : "r"(a[0]), "r"(a[1]), "r"(a[2]), "r"(a[3]), "r"(b[0]), "r"(b[1]));
}
// fp16 pack (round-to-nearest)
__device__ __forceinline__ unsigned pack_f16(float x, float y) {
    unsigned r;
    asm("cvt.rn.f16x2.f32 %0, %1, %2;" : "=r"(r) : "f"(y), "f"(x));
    return r;
}
// fp16 exact 2-term split of a pair
__device__ __forceinline__ void split_pair_f16(float x, float y, unsigned& hi, unsigned& lo) {
    hi = pack_f16(x, y);
    __half2 h = *reinterpret_cast<__half2*>(&hi);
    float2 hf = __half22float2(h);
    lo = pack_f16(x - hf.x, y - hf.y);
}

// ================= hgemm: BM=128 BN=128 BK=32, fp32 A (2-pass split) + fp16 W ====
// mode 0: fp32 C[r]=A[r]@W+bias(+resid)   mode 1: A gathered via list>>1 -> fp16 outh at e*TOK
// mode 5: dual launch: z selects {A,W,bias}; fp32 C slice z*TOK*N (used for K/V)
#define A128_STRIDE 40      // f16 elems (80 B)
#define B128_STRIDE 136     // f16 elems (272 B)
#define AH128 0
#define AL128 10240
#define BH128 20480
#define BUF128 29184        // AH + AL + BH(8704)
#define ROWP128 (2*BUF128)
#define SMEM128 (2*BUF128 + 1024 + 256)

extern "C" __global__ void __launch_bounds__(256, 2)
hgemm(const float* __restrict__ A, const __half* __restrict__ W16,
      const float* __restrict__ bias, const float* __restrict__ resid,
      float* __restrict__ C, __half* __restrict__ outh,
      int M, int N, int K, int lda,
      const int* __restrict__ list, const int* __restrict__ cntp,
      int mode, int relu,
      const float* A2, const __half* Wk16, const __half* Wv16,
      const float* bk2, const float* bv3) {
    extern __shared__ char sm_raw[];
    char* sm = (char*)(((ull)sm_raw + 127) & ~127ULL);

    int z = blockIdx.z;
    int e = (mode == 1) ? z : 0;
    const float* Asrc = A;
    const __half* Wsrc = W16;
    const float* bsrc = bias;
    if (mode == 5 && z > 0) {
        Asrc = A2;
        Wsrc = (z == 1) ? Wk16 : Wv16;
        bsrc = (z == 1) ? bk2 : bv3;
    }
    int rows = cntp ? cntp[e] : M;
    int m0 = blockIdx.y * 128;
    if (m0 >= rows) return;
    int n0 = blockIdx.x * 128;
    int tid = threadIdx.x;
    int lane = tid & 31, w = tid >> 5;
    int wm = w & 1, wn = w >> 1;

    const __half* We = Wsrc + (size_t)e * K * N;
    const float* be = bsrc + (size_t)e * N;

    const float** rowp = (const float**)(sm + ROWP128);
    if (tid < 128) {
        int r = m0 + tid;
        const float* p = nullptr;
        if (r < rows) {
            if (mode == 1) p = Asrc + (size_t)(list[e*TOK + r] >> 1) * lda;
            else           p = Asrc + (size_t)r * lda;
        }
        rowp[tid] = p;
    }
    __syncthreads();

    unsigned smbase = smem_u32(sm);
    int aq = lane >> 3, ar = lane & 7;
    unsigned a_base = smbase + AH128 +
        (unsigned)(((wm*64 + ar + 8*(aq & 1)) * A128_STRIDE + 8*(aq >> 1)) * 2);
    int bt = lane >> 3;
    int bkrow = (bt & 1)*8 + (lane & 7);
    int bnoff = (bt >> 1)*8;
    unsigned b_base = smbase + BH128 +
        (unsigned)((bkrow * B128_STRIDE + wn*32 + bnoff) * 2);

    float acc[4][4][4];
    #pragma unroll
    for (int i = 0; i < 4; i++)
        #pragma unroll
        for (int j = 0; j < 4; j++)
            #pragma unroll
            for (int q = 0; q < 4; q++) acc[i][j][q] = 0.f;

    int nch = K >> 5;
    float4 av[4];

    // ---- prologue: chunk 0 ----
    {
        unsigned bb = smbase;
        #pragma unroll
        for (int p = 0; p < 2; p++) {
            int s = tid + 256*p;
            CPA16(bb + BH128 + (s >> 4)*272 + (s & 15)*16,
                  (const char*)(We + (size_t)(s >> 4)*N + n0 + (s & 15)*8));
        }
        CPA_COMMIT();
        #pragma unroll
        for (int p = 0; p < 4; p++) {
            int s = tid + 256*p;
            const float* rp = rowp[s >> 3];
            av[p] = rp ? *(const float4*)(rp + (s & 7)*4) : make_float4(0.f,0.f,0.f,0.f);
        }
        char* bc = sm;
        #pragma unroll
        for (int p = 0; p < 4; p++) {
            int s = tid + 256*p;
            int m = s >> 3, kq = s & 7;
            unsigned h0, l0, h1, l1;
            split_pair_f16(av[p].x, av[p].y, h0, l0);
            split_pair_f16(av[p].z, av[p].w, h1, l1);
            unsigned aoff = (unsigned)(m*(A128_STRIDE*2) + kq*8);
            *(uint2*)(bc + AH128 + aoff) = make_uint2(h0, h1);
            *(uint2*)(bc + AL128 + aoff) = make_uint2(l0, l1);
        }
        CPA_WAIT0();
        __syncthreads();
    }

    for (int c = 0; c < nch; c++) {
        int buf = c & 1;
        bool has = (c + 1 < nch);
        if (has) {
            int kc = (c + 1) << 5;
            unsigned bb = smbase + (unsigned)((buf ^ 1) * BUF128);
            #pragma unroll
            for (int p = 0; p < 2; p++) {
                int s = tid + 256*p;
                CPA16(bb + BH128 + (s >> 4)*272 + (s & 15)*16,
                      (const char*)(We + (size_t)(kc + (s >> 4))*N + n0 + (s & 15)*8));
            }
            CPA_COMMIT();
            #pragma unroll
            for (int p = 0; p < 4; p++) {
                int s = tid + 256*p;
                const float* rp = rowp[s >> 3];
                av[p] = rp ? *(const float4*)(rp + kc + (s & 7)*4) : make_float4(0.f,0.f,0.f,0.f);
            }
        }
        unsigned bufo = (unsigned)(buf * BUF128);
        #pragma unroll
        for (int ks = 0; ks < 2; ks++) {
            unsigned ah[4][4], al[4][4], bf[2][4];
            unsigned ab = a_base + bufo + ks*32;
            unsigned bb2 = b_base + bufo + ks*16*(B128_STRIDE*2);
            #pragma unroll
            for (int i = 0; i < 4; i++) {
                ldm_x4(ah[i], ab + i*16*(A128_STRIDE*2));
                ldm_x4(al[i], ab + i*16*(A128_STRIDE*2) + (AL128 - AH128));
            }
            #pragma unroll
            for (int jj = 0; jj < 2; jj++) ldm_x4t(bf[jj], bb2 + jj*32);
            #pragma unroll
            for (int i = 0; i < 4; i++)
                #pragma unroll
                for (int j = 0; j < 4; j++) {
                    mma_f16(acc[i][j], ah[i], &bf[j >> 1][(j & 1)*2]);
                    mma_f16(acc[i][j], al[i], &bf[j >> 1][(j & 1)*2]);
                }
        }
        if (has) {
            char* bc = sm + (buf ^ 1) * BUF128;
            #pragma unroll
            for (int p = 0; p < 4; p++) {
                int s = tid + 256*p;
                int m = s >> 3, kq = s & 7;
                unsigned h0, l0, h1, l1;
                split_pair_f16(av[p].x, av[p].y, h0, l0);
                split_pair_f16(av[p].z, av[p].w, h1, l1);
                unsigned aoff = (unsigned)(m*(A128_STRIDE*2) + kq*8);
                *(uint2*)(bc + AH128 + aoff) = make_uint2(h0, h1);
                *(uint2*)(bc + AL128 + aoff) = make_uint2(l0, l1);
            }
            CPA_WAIT0();
        }
        __syncthreads();
    }

    // ---- epilogue ----
    #pragma unroll
    for (int i = 0; i < 4; i++) {
        int r0 = m0 + wm*64 + 16*i + (lane >> 2);
        #pragma unroll
        for (int hf = 0; hf < 2; hf++) {
            int row = r0 + hf*8;
            if (row >= rows) continue;
            float* crow = nullptr;
            __half* orow = nullptr;
            const float* rsd = nullptr;
            if (mode == 0) {
                crow = C + (size_t)row * N;
                if (resid) rsd = resid + (size_t)row * N;
            } else if (mode == 5) {
                crow = C + (size_t)z*TOK*N + (size_t)row * N;
            } else { // mode 1: fp16 out
                orow = outh + ((size_t)e*TOK + row) * N;
            }
            #pragma unroll
            for (int j = 0; j < 4; j++) {
                int col = n0 + wn*32 + 8*j + 2*(lane & 3);
                float v0 = acc[i][j][hf*2 + 0];
                float v1 = acc[i][j][hf*2 + 1];
                v0 += be[col]; v1 += be[col + 1];
                if (rsd) { v0 += rsd[col]; v1 += rsd[col + 1]; }
                if (relu) { v0 = fmaxf(v0, 0.f); v1 = fmaxf(v1, 0.f); }
                if (crow) *(float2*)(crow + col) = make_float2(v0, v1);
                else      *(unsigned*)(orow + col) = pack_f16(v0, v1);
            }
        }
    }
}

// ================= hgemm_h: fp16 A (single plane) + fp16 W, 32 MMAs/chunk ========
// mode 2: A at e*TOK -> fp16 outh at e*TOK (+relu)   mode 3: A at e*TOK -> fp32 scatter
#define AH_H  0
#define BH_H  10240
#define BUFH  18944        // A(10240) + B(8704)
#define SMEMH (2*BUFH + 256)

extern "C" __global__ void __launch_bounds__(256, 2)
hgemm_h(const __half* __restrict__ Ah, const __half* __restrict__ W16,
        const float* __restrict__ bias,
        float* __restrict__ C, __half* __restrict__ outh,
        int N, int K, int lda,
        const int* __restrict__ list, const int* __restrict__ cntp,
        int mode, int relu) {
    extern __shared__ char sm_raw[];
    char* sm = (char*)(((ull)sm_raw + 127) & ~127ULL);

    int e = blockIdx.z;
    int rows = cntp[e];
    int m0 = blockIdx.y * 128;
    if (m0 >= rows) return;
    int n0 = blockIdx.x * 128;
    int tid = threadIdx.x;
    int lane = tid & 31, w = tid >> 5;
    int wm = w & 1, wn = w >> 1;

    const __half* Ae = Ah + ((size_t)e*TOK + m0) * lda;
    const __half* We = W16 + (size_t)e * K * N;
    const float* be = bias + (size_t)e * N;

    unsigned smbase = smem_u32(sm);
    int aq = lane >> 3, ar = lane & 7;
    unsigned a_base = smbase + AH_H +
        (unsigned)(((wm*64 + ar + 8*(aq & 1)) * A128_STRIDE + 8*(aq >> 1)) * 2);
    int bt = lane >> 3;
    int bkrow = (bt & 1)*8 + (lane & 7);
    int bnoff = (bt >> 1)*8;
    unsigned b_base = smbase + BH_H +
        (unsigned)((bkrow * B128_STRIDE + wn*32 + bnoff) * 2);

    float acc[4][4][4];
    #pragma unroll
    for (int i = 0; i < 4; i++)
        #pragma unroll
        for (int j = 0; j < 4; j++)
            #pragma unroll
            for (int q = 0; q < 4; q++) acc[i][j][q] = 0.f;

    int nch = K >> 5;

    // stage chunk kc into buffer bb: A 512 granules + B 512 granules, 2+2 per thread
    #define H_STAGE(kc_, bb_) do { \
        _Pragma("unroll") \
        for (int p = 0; p < 2; p++) { \
            int g = tid + 256*p; \
            CPA16((bb_) + AH_H + (g >> 2)*80 + (g & 3)*16, \
                  (const char*)(Ae + (size_t)(g >> 2)*lda + (kc_) + (g & 3)*8)); \
            CPA16((bb_) + BH_H + (g >> 4)*272 + (g & 15)*16, \
                  (const char*)(We + (size_t)((kc_) + (g >> 4))*N + n0 + (g & 15)*8)); \
        } \
        CPA_COMMIT(); \
    } while (0)

    H_STAGE(0, smbase);
    CPA_WAIT0();
    __syncthreads();

    for (int c = 0; c < nch; c++) {
        int buf = c & 1;
        bool has = (c + 1 < nch);
        if (has) H_STAGE((c + 1) << 5, smbase + (unsigned)((buf ^ 1) * BUFH));

        unsigned bufo = (unsigned)(buf * BUFH);
        #pragma unroll
        for (int ks = 0; ks < 2; ks++) {
            unsigned ah[4][4], bf[2][4];
            unsigned ab = a_base + bufo + ks*32;
            unsigned bb2 = b_base + bufo + ks*16*(B128_STRIDE*2);
            #pragma unroll
            for (int i = 0; i < 4; i++) ldm_x4(ah[i], ab + i*16*(A128_STRIDE*2));
            #pragma unroll
            for (int jj = 0; jj < 2; jj++) ldm_x4t(bf[jj], bb2 + jj*32);
            #pragma unroll
            for (int i = 0; i < 4; i++)
                #pragma unroll
                for (int j = 0; j < 4; j++)
                    mma_f16(acc[i][j], ah[i], &bf[j >> 1][(j & 1)*2]);
        }
        if (has) CPA_WAIT0();
        __syncthreads();
    }
    #undef H_STAGE

    // ---- epilogue ----
    #pragma unroll
    for (int i = 0; i < 4; i++) {
        int r0 = m0 + wm*64 + 16*i + (lane >> 2);
        #pragma unroll
        for (int hf = 0; hf < 2; hf++) {
            int row = r0 + hf*8;
            if (row >= rows) continue;
            float* crow = nullptr;
            __half* orow = nullptr;
            if (mode == 3) {
                int ent = list[e*TOK + row];
                crow = C + (size_t)(ent & 1)*TOK*N + (size_t)(ent >> 1)*N;
            } else {
                orow = outh + ((size_t)e*TOK + row) * N;
            }
            #pragma unroll
            for (int j = 0; j < 4; j++) {
                int col = n0 + wn*32 + 8*j + 2*(lane & 3);
                float v0 = acc[i][j][hf*2 + 0];
                float v1 = acc[i][j][hf*2 + 1];
                v0 += be[col]; v1 += be[col + 1];
                if (relu) { v0 = fmaxf(v0, 0.f); v1 = fmaxf(v1, 0.f); }
                if (crow) *(float2*)(crow + col) = make_float2(v0, v1);
                else      *(unsigned*)(orow + col) = pack_f16(v0, v1);
            }
        }
    }
}

// ================= hgemm_wl: BM=32 BN=256 BK=32, split-K=4, fp16 2-pass =========
#define AW_STRIDE 40
#define BW_STRIDE 264
#define AHW 0
#define ALW 2560
#define BHW 5120
#define BUFW 22016          // 5120 + 16896
#define SMEMW (2*BUFW + 256)

extern "C" __global__ void __launch_bounds__(256)
hgemm_wl(const float* __restrict__ A, const float* __restrict__ W,
         float* __restrict__ part) {
    extern __shared__ char sm_raw[];
    char* sm = (char*)(((ull)sm_raw + 127) & ~127ULL);

    int n0 = blockIdx.x * 256;
    int z  = blockIdx.y;
    int tid = threadIdx.x;
    int lane = tid & 31, w = tid >> 5;

    const float* Ab = A + (size_t)z * WLKC;
    const float* Wb = W + (size_t)z * WLKC * NBIG;

    unsigned smbase = smem_u32(sm);
    int aq = lane >> 3, ar = lane & 7;
    unsigned a_base = smbase + AHW +
        (unsigned)(((ar + 8*(aq & 1)) * AW_STRIDE + 8*(aq >> 1)) * 2);
    unsigned b_base = smbase + BHW +
        (unsigned)(((lane & 15) * BW_STRIDE + w*32) * 2);

    float acc[2][4][4];
    #pragma unroll
    for (int i = 0; i < 2; i++)
        #pragma unroll
        for (int j = 0; j < 4; j++)
            #pragma unroll
            for (int q = 0; q < 4; q++) acc[i][j][q] = 0.f;

    const int nch = WLKC >> 5;   // 128
    float4 av1; float4 bv[8];

    {
        int m = tid >> 3, kq = tid & 7;
        av1 = *(const float4*)(Ab + (size_t)m*NBIG + kq*4);
        #pragma unroll
        for (int p = 0; p < 8; p++) {
            int s = tid + 256*p;
            bv[p] = *(const float4*)(Wb + (size_t)(s >> 6)*NBIG + n0 + (s & 63)*4);
        }
        char* bb = sm;
        unsigned h0, l0, h1, l1;
        split_pair_f16(av1.x, av1.y, h0, l0);
        split_pair_f16(av1.z, av1.w, h1, l1);
        unsigned aoff = (unsigned)(m*(AW_STRIDE*2) + kq*8);
        *(uint2*)(bb + AHW + aoff) = make_uint2(h0, h1);
        *(uint2*)(bb + ALW + aoff) = make_uint2(l0, l1);
        #pragma unroll
        for (int p = 0; p < 8; p++) {
            int s = tid + 256*p;
            int n4 = s & 63, kk = s >> 6;
            unsigned bh0 = pack_f16(bv[p].x, bv[p].y);
            unsigned bh1 = pack_f16(bv[p].z, bv[p].w);
            unsigned boff = (unsigned)(kk*(BW_STRIDE*2) + n4*8);
            *(uint2*)(bb + BHW + boff) = make_uint2(bh0, bh1);
        }
    }
    __syncthreads();

    for (int c = 0; c < nch; c++) {
        int buf = c & 1;
        bool has = (c + 1 < nch);
        if (has) {
            int kc = (c + 1) << 5;
            int m = tid >> 3, kq = tid & 7;
            av1 = *(const float4*)(Ab + (size_t)m*NBIG + kc + kq*4);
            #pragma unroll
            for (int p = 0; p < 8; p++) {
                int s = tid + 256*p;
                bv[p] = *(const float4*)(Wb + (size_t)(kc + (s >> 6))*NBIG + n0 + (s & 63)*4);
            }
        }
        unsigned bufo = (unsigned)(buf * BUFW);
        #pragma unroll
        for (int ks = 0; ks < 2; ks++) {
            unsigned ah[2][4], al[2][4], bh[4][2];
            unsigned ab = a_base + bufo + ks*32;
            unsigned bb2 = b_base + bufo + ks*16*(BW_STRIDE*2);
            #pragma unroll
            for (int i = 0; i < 2; i++) {
                ldm_x4(ah[i], ab + i*16*(AW_STRIDE*2));
                ldm_x4(al[i], ab + i*16*(AW_STRIDE*2) + (ALW - AHW));
            }
            #pragma unroll
            for (int j = 0; j < 4; j++) ldm_x2t(bh[j], bb2 + j*16);
            #pragma unroll
            for (int i = 0; i < 2; i++)
                #pragma unroll
                for (int j = 0; j < 4; j++) {
                    mma_f16(acc[i][j], ah[i], bh[j]);
                    mma_f16(acc[i][j], al[i], bh[j]);
                }
        }
        if (has) {
            char* bb = sm + (buf ^ 1) * BUFW;
            int m = tid >> 3, kq = tid & 7;
            unsigned h0, l0, h1, l1;
            split_pair_f16(av1.x, av1.y, h0, l0);
            split_pair_f16(av1.z, av1.w, h1, l1);
            unsigned aoff = (unsigned)(m*(AW_STRIDE*2) + kq*8);
            *(uint2*)(bb + AHW + aoff) = make_uint2(h0, h1);
            *(uint2*)(bb + ALW + aoff) = make_uint2(l0, l1);
            #pragma unroll
            for (int p = 0; p < 8; p++) {
                int s = tid + 256*p;
                int n4 = s & 63, kk = s >> 6;
                unsigned bh0 = pack_f16(bv[p].x, bv[p].y);
                unsigned bh1 = pack_f16(bv[p].z, bv[p].w);
                unsigned boff = (unsigned)(kk*(BW_STRIDE*2) + n4*8);
                *(uint2*)(bb + BHW + boff) = make_uint2(bh0, bh1);
            }
        }
        __syncthreads();
    }

    float* pz = part + (size_t)z * 32 * NBIG;
    #pragma unroll
    for (int i = 0; i < 2; i++) {
        int r0 = 16*i + (lane >> 2);
        #pragma unroll
        for (int hf = 0; hf < 2; hf++) {
            int row = r0 + hf*8;
            float* crow = pz + (size_t)row * NBIG;
            #pragma unroll
            for (int j = 0; j < 4; j++) {
                int col = n0 + w*32 + 8*j + 2*(lane & 3);
                *(float2*)(crow + col) =
                    make_float2(acc[i][j][hf*2 + 0], acc[i][j][hf*2 + 1]);
            }
        }
    }
}

// ---------------- weight conversion (vectorized) ----------------
__global__ void cvt_moe_w(const float* __restrict__ W1, const float* __restrict__ Ws,
                          const float* __restrict__ W2, __half* __restrict__ o1,
                          __half* __restrict__ os, __half* __restrict__ o2) {
    size_t i = ((size_t)blockIdx.x * 256 + threadIdx.x) * 4;
    const size_t n1 = (size_t)NEXP*DMODEL*FEXP;
    const size_t ns = (size_t)NEXP*FEXP*FEXP;
    const float* s; __half* d; size_t j;
    if (i < n1)            { s = W1; d = o1; j = i; }
    else if (i < n1 + ns)  { s = Ws; d = os; j = i - n1; }
    else                   { s = W2; d = o2; j = i - n1 - ns; }
    float4 v = *(const float4*)(s + j);
    *(__half2*)(d + j)     = __floats2half2_rn(v.x, v.y);
    *(__half2*)(d + j + 2) = __floats2half2_rn(v.z, v.w);
}
__global__ void cvt_qkvo_w(const float* __restrict__ Wq, const float* __restrict__ Wk,
                           const float* __restrict__ Wv, const float* __restrict__ Wo,
                           __half* __restrict__ oq, __half* __restrict__ ok,
                           __half* __restrict__ ov, __half* __restrict__ oo) {
    size_t i = ((size_t)blockIdx.x * 256 + threadIdx.x) * 4;
    int seg = (int)(i >> 16);
    size_t j = i & 65535;
    const float* s = (seg == 0) ? Wq : (seg == 1) ? Wk : (seg == 2) ? Wv : Wo;
    __half* d = (seg == 0) ? oq : (seg == 1) ? ok : (seg == 2) ? ov : oo;
    float4 v = *(const float4*)(s + j);
    *(__half2*)(d + j)     = __floats2half2_rn(v.x, v.y);
    *(__half2*)(d + j + 2) = __floats2half2_rn(v.z, v.w);
}

// ---------------- rmsnorm: 1 warp per row, 8 rows/block ----------------
__global__ void rmsnorm_kernel(const float* __restrict__ in, const float* __restrict__ w,
                               float* __restrict__ out) {
    int row = blockIdx.x * 8 + (threadIdx.x >> 5);
    int lane = threadIdx.x & 31;
    const float* ip = in + (size_t)row * DMODEL;
    float4 v0 = *(const float4*)(ip + lane*4);
    float4 v1 = *(const float4*)(ip + 128 + lane*4);
    float ss = v0.x*v0.x + v0.y*v0.y + v0.z*v0.z + v0.w*v0.w
             + v1.x*v1.x + v1.y*v1.y + v1.z*v1.z + v1.w*v1.w;
    #pragma unroll
    for (int o = 16; o > 0; o >>= 1) ss += __shfl_xor_sync(0xffffffffu, ss, o);
    float sc = rsqrtf(ss * (1.0f/256.0f) + 1e-5f);
    float4 w0 = *(const float4*)(w + lane*4);
    float4 w1 = *(const float4*)(w + 128 + lane*4);
    float* op = out + (size_t)row * DMODEL;
    *(float4*)(op + lane*4) =
        make_float4(v0.x*sc*w0.x, v0.y*sc*w0.y, v0.z*sc*w0.z, v0.w*sc*w0.w);
    *(float4*)(op + 128 + lane*4) =
        make_float4(v1.x*sc*w1.x, v1.y*sc*w1.y, v1.z*sc*w1.z, v1.w*sc*w1.w);
}

// ---------------- Wl split-K reduce ----------------
__global__ void wl_reduce(const float* __restrict__ part, const float* __restrict__ bl,
                          float* __restrict__ lat) {
    int i = blockIdx.x * 256 + threadIdx.x;
    float s = bl[i & (NBIG-1)];
    #pragma unroll
    for (int p = 0; p < WLSPLIT; p++) s += part[(size_t)p*32*NBIG + i];
    lat[i] = s;
}

// ---------------- attention ----------------
__global__ void attn_kernel(const float* __restrict__ q, const float* __restrict__ k,
                            const float* __restrict__ v, float* __restrict__ ao) {
    int bh = blockIdx.x;
    int b = bh >> 3, h = bh & 7;
    int s = threadIdx.x;
    __shared__ float ks[64][32];
    __shared__ float vs[64][32];
    for (int idx = s; idx < 2048; idx += 64) {
        int l = idx >> 5, d = idx & 31;
        size_t src = (size_t)(b*64 + l)*DMODEL + h*32 + d;
        ks[l][d] = k[src];
        vs[l][d] = v[src];
    }
    __syncthreads();

    float qr[32];
    const float* qp = q + (size_t)(b*64 + s)*DMODEL + h*32;
    #pragma unroll
    for (int d = 0; d < 32; d++) qr[d] = qp[d];

    // RoPE (bug-faithful: imaginary part uses the updated real part)
    #pragma unroll
    for (int i = 0; i < 16; i++) {
        float fr = powf(10000.0f, -(float)i / 16.0f);
        float ang = (float)s * fr;
        float c = cosf(ang), sn = sinf(ang);
        float X = qr[2*i], Y = qr[2*i + 1];
        float nX = X*c - Y*sn;
        float nY = nX*sn + Y*c;
        qr[2*i] = nX; qr[2*i + 1] = nY;
    }

    const float scale = 0.1767766952966369f;
    float sc[64];
    float mx = -1e30f;
    #pragma unroll
    for (int l = 0; l < 64; l++) {
        float p = 0.f;
        #pragma unroll
        for (int d = 0; d < 32; d++) p += qr[d] * ks[l][d];
        p *= scale;
        sc[l] = p;
        mx = fmaxf(mx, p);
    }
    float se = 0.f;
    #pragma unroll
    for (int l = 0; l < 64; l++) { sc[l] = __expf(sc[l] - mx); se += sc[l]; }
    float inv = 1.0f / se;

    float* op = ao + (size_t)(b*64 + s)*DMODEL + h*32;
    #pragma unroll
    for (int d = 0; d < 32; d++) {
        float a = 0.f;
        #pragma unroll
        for (int l = 0; l < 64; l++) a += sc[l] * vs[l][d];
        op[d] = a * inv;
    }
}

// ---------------- router ----------------
__global__ void zero_cnt_kernel(int* cnt) { if (threadIdx.x < NEXP) cnt[threadIdx.x] = 0; }

__global__ void route_kernel(const float* __restrict__ y2, const float* __restrict__ rw,
                             const float* __restrict__ rb, float* __restrict__ topv,
                             int* __restrict__ cnt, int* __restrict__ list) {
    int tok = blockIdx.x, lane = threadIdx.x;
    float xv[8];
    #pragma unroll
    for (int j = 0; j < 8; j++) xv[j] = y2[(size_t)tok*DMODEL + j*32 + lane];
    float lg[8];
    #pragma unroll
    for (int e = 0; e < 8; e++) {
        float p = 0.f;
        #pragma unroll
        for (int j = 0; j < 8; j++) p += xv[j] * rw[(j*32 + lane)*NEXP + e];
        #pragma unroll
        for (int o = 16; o > 0; o >>= 1) p += __shfl_xor_sync(0xffffffffu, p, o);
        lg[e] = p;
    }
    if (lane == 0) {
        float mx = -1e30f;
        #pragma unroll
        for (int e = 0; e < 8; e++) { lg[e] += rb[e]; mx = fmaxf(mx, lg[e]); }
        float se = 0.f, pr[8];
        #pragma unroll
        for (int e = 0; e < 8; e++) { pr[e] = __expf(lg[e] - mx); se += pr[e]; }
        float inv = 1.0f / se;
        #pragma unroll
        for (int e = 0; e < 8; e++) pr[e] *= inv;
        int b0 = 0; float v0 = -1.f;
        #pragma unroll
        for (int e = 0; e < 8; e++) if (pr[e] > v0) { v0 = pr[e]; b0 = e; }
        int b1 = -1; float v1 = -1.f;
        #pragma unroll
        for (int e = 0; e < 8; e++) if (e != b0 && pr[e] > v1) { v1 = pr[e]; b1 = e; }
        topv[tok*2 + 0] = v0;
        topv[tok*2 + 1] = v1;
        int p0 = atomicAdd(&cnt[b0], 1); list[b0*TOK + p0] = tok*2;
        int p1 = atomicAdd(&cnt[b1], 1); list[b1*TOK + p1] = tok*2 + 1;
    }
}

// ---------------- combine ----------------
__global__ void combine_kernel(const float* __restrict__ x2, const float* __restrict__ topv,
                               const float* __restrict__ eo, float* __restrict__ out) {
    int tok = blockIdx.x, d = threadIdx.x;
    size_t i = (size_t)tok*DMODEL + d;
    out[i] = x2[i] + topv[tok*2] * eo[i] + topv[tok*2 + 1] * eo[(size_t)TOK*DMODEL + i];
}

// ---------------- host ----------------
extern "C" void kernel_launch(void* const* d_in, const int* in_sizes, int n_in,
                              void* d_out, int out_size) {
    const float* x   = (const float*)d_in[0];
    const float* r1w = (const float*)d_in[1];
    const float* Wl  = (const float*)d_in[2];
    const float* bl  = (const float*)d_in[3];
    const float* Wq  = (const float*)d_in[4];
    const float* bq  = (const float*)d_in[5];
    const float* Wk  = (const float*)d_in[6];
    const float* bk  = (const float*)d_in[7];
    const float* Wv  = (const float*)d_in[8];
    const float* bv  = (const float*)d_in[9];
    const float* Wo  = (const float*)d_in[10];
    const float* bo  = (const float*)d_in[11];
    const float* r2w = (const float*)d_in[12];
    const float* rw  = (const float*)d_in[13];
    const float* rb  = (const float*)d_in[14];
    const float* W1  = (const float*)d_in[15];
    const float* b1  = (const float*)d_in[16];
    const float* Wsx = (const float*)d_in[17];
    const float* bs  = (const float*)d_in[18];
    const float* W2  = (const float*)d_in[19];
    const float* b2  = (const float*)d_in[20];

    float *y1, *part, *lat, *qkv, *ao, *x2, *y2, *topv, *eo;
    __half *h1x, *h2x, *w116, *ws16, *w216, *wq16, *wk16, *wv16, *wo16;
    int *cnt, *list;
    cudaGetSymbolAddress((void**)&y1,   g_y1);
    cudaGetSymbolAddress((void**)&part, g_part);
    cudaGetSymbolAddress((void**)&lat,  g_lat);
    cudaGetSymbolAddress((void**)&qkv,  g_qkv);
    cudaGetSymbolAddress((void**)&ao,   g_ao);
    cudaGetSymbolAddress((void**)&x2,   g_x2);
    cudaGetSymbolAddress((void**)&y2,   g_y2);
    cudaGetSymbolAddress((void**)&topv, g_topv);
    cudaGetSymbolAddress((void**)&cnt,  g_cnt);
    cudaGetSymbolAddress((void**)&list, g_list);
    cudaGetSymbolAddress((void**)&eo,   g_eo);
    cudaGetSymbolAddress((void**)&h1x,  g_h1x);
    cudaGetSymbolAddress((void**)&h2x,  g_h2x);
    cudaGetSymbolAddress((void**)&w116, g_w116);
    cudaGetSymbolAddress((void**)&ws16, g_ws16);
    cudaGetSymbolAddress((void**)&w216, g_w216);
    cudaGetSymbolAddress((void**)&wq16, g_wq16);
    cudaGetSymbolAddress((void**)&wk16, g_wk16);
    cudaGetSymbolAddress((void**)&wv16, g_wv16);
    cudaGetSymbolAddress((void**)&wo16, g_wo16);

    static int inited = 0;
    static cudaStream_t s1, s2;
    static cudaEvent_t evFork, evCvt, evRms1, evQ;
    if (!inited) {
        cudaFuncSetAttribute(hgemm,    cudaFuncAttributeMaxDynamicSharedMemorySize, SMEM128);
        cudaFuncSetAttribute(hgemm_h,  cudaFuncAttributeMaxDynamicSharedMemorySize, SMEMH);
        cudaFuncSetAttribute(hgemm_wl, cudaFuncAttributeMaxDynamicSharedMemorySize, SMEMW);
        cudaStreamCreateWithFlags(&s1, cudaStreamNonBlocking);
        cudaStreamCreateWithFlags(&s2, cudaStreamNonBlocking);
        cudaEventCreateWithFlags(&evFork, cudaEventDisableTiming);
        cudaEventCreateWithFlags(&evCvt,  cudaEventDisableTiming);
        cudaEventCreateWithFlags(&evRms1, cudaEventDisableTiming);
        cudaEventCreateWithFlags(&evQ,    cudaEventDisableTiming);
        inited = 1;
    }

    // ---- side stream s1: weight cvt + cnt zero (off critical path) ----
    cudaEventRecord(evFork, 0);
    cudaStreamWaitEvent(s1, evFork, 0);
    cvt_qkvo_w<<<256, 256, 0, s1>>>(Wq, Wk, Wv, Wo, wq16, wk16, wv16, wo16);
    cvt_moe_w<<<12288, 256, 0, s1>>>(W1, Wsx, W2, w116, ws16, w216);
    zero_cnt_kernel<<<1, 32, 0, s1>>>(cnt);
    cudaEventRecord(evCvt, s1);

    // ---- main chain ----
    rmsnorm_kernel<<<TOK/8, 256>>>(x, r1w, y1);
    cudaEventRecord(evRms1, 0);

    // ---- s2: Q projection overlapping Wl ----
    cudaStreamWaitEvent(s2, evRms1, 0);
    cudaStreamWaitEvent(s2, evCvt, 0);
    hgemm<<<dim3(2, 16, 1), 256, SMEM128, s2>>>(y1, wq16, bq, nullptr, qkv, nullptr,
        TOK, DMODEL, DMODEL, DMODEL, nullptr, nullptr, 0, 0,
        nullptr, nullptr, nullptr, nullptr, nullptr);
    cudaEventRecord(evQ, s2);

    hgemm_wl<<<dim3(64, WLSPLIT), 256, SMEMW>>>(y1, Wl, part);
    wl_reduce<<<TOK, 256>>>(part, bl, lat);

    // K/V: mode 5, z=0 -> K(lat,wk16,bk) slice 1, z=1 -> V(lat,wv16,bv) slice 2
    cudaStreamWaitEvent(0, evCvt, 0);
    hgemm<<<dim3(2, 16, 2), 256, SMEM128>>>(lat, wk16, bk, nullptr, qkv + (size_t)TOK*DMODEL,
        nullptr, TOK, DMODEL, DMODEL, DMODEL, nullptr, nullptr, 5, 0,
        lat, wv16, wv16, bv, bv);

    cudaStreamWaitEvent(0, evQ, 0);
    attn_kernel<<<256, 64>>>(qkv, qkv + (size_t)TOK*DMODEL, qkv + 2*(size_t)TOK*DMODEL, ao);
    hgemm<<<dim3(2, 16, 1), 256, SMEM128>>>(ao, wo16, bo, x, x2, nullptr,
        TOK, DMODEL, DMODEL, DMODEL, nullptr, nullptr, 0, 0,
        nullptr, nullptr, nullptr, nullptr, nullptr);

    // --- MoE ---
    rmsnorm_kernel<<<TOK/8, 256>>>(x2, r2w, y2);
    route_kernel<<<TOK, 32>>>(y2, rw, rb, topv, cnt, list);
    // L1: fp32 y2 (2-pass A) -> fp16 h1x
    hgemm<<<dim3(8, 16, NEXP), 256, SMEM128>>>(y2, w116, b1, nullptr, nullptr, h1x,
        0, FEXP, DMODEL, DMODEL, list, cnt, 1, 0,
        nullptr, nullptr, nullptr, nullptr, nullptr);
    // L2: fp16 h1x (1-pass A) -> fp16 h2x (+relu)
    hgemm_h<<<dim3(8, 16, NEXP), 256, SMEMH>>>(h1x, ws16, bs, nullptr, h2x,
        FEXP, FEXP, FEXP, list, cnt, 2, 1);
    // L3: fp16 h2x (1-pass A) -> fp32 scattered eo
    hgemm_h<<<dim3(2, 16, NEXP), 256, SMEMH>>>(h2x, w216, b2, eo, nullptr,
        DMODEL, FEXP, FEXP, list, cnt, 3, 0);
    combine_kernel<<<TOK, 256>>>(x2, topv, eo, (float*)d_out);
}

// round 17
// speedup vs baseline: 1.3497x; 1.0004x over previous
#include <cuda_runtime.h>
#include <cuda_bf16.h>
#include <cuda_fp16.h>

typedef unsigned long long ull;

// B=32, S=64, D=256, H=8, E=8, topk=2, F=1024, LATENT=64, HD=32
#define TOK      2048
#define DMODEL   256
#define NBIG     16384
#define FEXP     1024
#define NEXP     8
#define WLSPLIT  4
#define WLKC     (NBIG/WLSPLIT)   // 4096

// ---------------- scratch ----------------
__device__ float  g_y1 [TOK*DMODEL];
__device__ __align__(16) __half g_y1h[TOK*DMODEL];
__device__ float  g_part[WLSPLIT*32*NBIG];
__device__ __align__(16) __half g_lath[TOK*DMODEL];
__device__ float  g_qkv[3*TOK*DMODEL];
__device__ __align__(16) __half g_aoh[TOK*DMODEL];
__device__ float  g_x2 [TOK*DMODEL];
__device__ float  g_y2 [TOK*DMODEL];
__device__ float  g_topv[TOK*2];
__device__ int    g_cnt[NEXP];
__device__ int    g_list[NEXP*TOK];
__device__ float  g_eo [2*TOK*DMODEL];
__device__ __align__(16) __half g_h1x[NEXP*TOK*FEXP];
__device__ __align__(16) __half g_h2x[NEXP*TOK*FEXP];
__device__ __align__(16) __half g_w116[NEXP*DMODEL*FEXP];
__device__ __align__(16) __half g_ws16[NEXP*FEXP*FEXP];
__device__ __align__(16) __half g_w216[NEXP*FEXP*DMODEL];
__device__ __align__(16) __half g_wq16[DMODEL*DMODEL];
__device__ __align__(16) __half g_wk16[DMODEL*DMODEL];
__device__ __align__(16) __half g_wv16[DMODEL*DMODEL];
__device__ __align__(16) __half g_wo16[DMODEL*DMODEL];

// ---------------- helpers ----------------
__device__ __forceinline__ unsigned smem_u32(const void* p) {
    return (unsigned)__cvta_generic_to_shared(p);
}
#define CPA16(dst, src) asm volatile("cp.async.cg.shared.global [%0], [%1], 16;" :: "r"(dst), "l"(src))
#define CPA_COMMIT()    asm volatile("cp.async.commit_group;")
#define CPA_WAIT0()     asm volatile("cp.async.wait_group 0;")
__device__ __forceinline__ void ldm_x4(unsigned* r, unsigned addr) {
    asm volatile("ldmatrix.sync.aligned.m8n8.x4.shared.b16 {%0,%1,%2,%3}, [%4];"
        : "=r"(r[0]), "=r"(r[1]), "=r"(r[2]), "=r"(r[3]) : "r"(addr));
}
__device__ __forceinline__ void ldm_x4t(unsigned* r, unsigned addr) {
    asm volatile("ldmatrix.sync.aligned.m8n8.x4.trans.shared.b16 {%0,%1,%2,%3}, [%4];"
        : "=r"(r[0]), "=r"(r[1]), "=r"(r[2]), "=r"(r[3]) : "r"(addr));
}
__device__ __forceinline__ void ldm_x2t(unsigned* r, unsigned addr) {
    asm volatile("ldmatrix.sync.aligned.m8n8.x2.trans.shared.b16 {%0,%1}, [%2];"
        : "=r"(r[0]), "=r"(r[1]) : "r"(addr));
}
__device__ __forceinline__ void mma_f16(float* c, const unsigned* a, const unsigned* b) {
    asm volatile("mma.sync.aligned.m16n8k16.row.col.f32.f16.f16.f32 "
        "{%0,%1,%2,%3}, {%4,%5,%6,%7}, {%8,%9}, {%0,%1,%2,%3};"
        : "+f"(c[0]), "+f"(c[1]), "+f"(c[2]), "+f"(c[3])
        : "r"(a[0]), "r"(a[1]), "r"(a[2]), "r"(a[3]), "r"(b[0]), "r"(b[1]));
}
// fp16 pack (round-to-nearest)
__device__ __forceinline__ unsigned pack_f16(float x, float y) {
    unsigned r;
    asm("cvt.rn.f16x2.f32 %0, %1, %2;" : "=r"(r) : "f"(y), "f"(x));
    return r;
}
// fp16 exact 2-term split of a pair
__device__ __forceinline__ void split_pair_f16(float x, float y, unsigned& hi, unsigned& lo) {
    hi = pack_f16(x, y);
    __half2 h = *reinterpret_cast<__half2*>(&hi);
    float2 hf = __half22float2(h);
    lo = pack_f16(x - hf.x, y - hf.y);
}

// ================= hgemm: BM=128 BN=128 BK=32, fp32 A (2-pass split) + fp16 W ====
// mode 1: A gathered via list>>1 -> fp16 outh at e*TOK  (MoE L1)
#define A128_STRIDE 40      // f16 elems (80 B)
#define B128_STRIDE 136     // f16 elems (272 B)
#define AH128 0
#define AL128 10240
#define BH128 20480
#define BUF128 29184        // AH + AL + BH(8704)
#define ROWP128 (2*BUF128)
#define SMEM128 (2*BUF128 + 1024 + 256)

extern "C" __global__ void __launch_bounds__(256, 2)
hgemm(const float* __restrict__ A, const __half* __restrict__ W16,
      const float* __restrict__ bias,
      __half* __restrict__ outh,
      int N, int K, int lda,
      const int* __restrict__ list, const int* __restrict__ cntp,
      int relu) {
    extern __shared__ char sm_raw[];
    char* sm = (char*)(((ull)sm_raw + 127) & ~127ULL);

    int e = blockIdx.z;
    int rows = cntp[e];
    int m0 = blockIdx.y * 128;
    if (m0 >= rows) return;
    int n0 = blockIdx.x * 128;
    int tid = threadIdx.x;
    int lane = tid & 31, w = tid >> 5;
    int wm = w & 1, wn = w >> 1;

    const __half* We = W16 + (size_t)e * K * N;
    const float* be = bias + (size_t)e * N;

    const float** rowp = (const float**)(sm + ROWP128);
    if (tid < 128) {
        int r = m0 + tid;
        const float* p = nullptr;
        if (r < rows) p = A + (size_t)(list[e*TOK + r] >> 1) * lda;
        rowp[tid] = p;
    }
    __syncthreads();

    unsigned smbase = smem_u32(sm);
    int aq = lane >> 3, ar = lane & 7;
    unsigned a_base = smbase + AH128 +
        (unsigned)(((wm*64 + ar + 8*(aq & 1)) * A128_STRIDE + 8*(aq >> 1)) * 2);
    int bt = lane >> 3;
    int bkrow = (bt & 1)*8 + (lane & 7);
    int bnoff = (bt >> 1)*8;
    unsigned b_base = smbase + BH128 +
        (unsigned)((bkrow * B128_STRIDE + wn*32 + bnoff) * 2);

    float acc[4][4][4];
    #pragma unroll
    for (int i = 0; i < 4; i++)
        #pragma unroll
        for (int j = 0; j < 4; j++)
            #pragma unroll
            for (int q = 0; q < 4; q++) acc[i][j][q] = 0.f;

    int nch = K >> 5;
    float4 av[4];

    // ---- prologue: chunk 0 ----
    {
        unsigned bb = smbase;
        #pragma unroll
        for (int p = 0; p < 2; p++) {
            int s = tid + 256*p;
            CPA16(bb + BH128 + (s >> 4)*272 + (s & 15)*16,
                  (const char*)(We + (size_t)(s >> 4)*N + n0 + (s & 15)*8));
        }
        CPA_COMMIT();
        #pragma unroll
        for (int p = 0; p < 4; p++) {
            int s = tid + 256*p;
            const float* rp = rowp[s >> 3];
            av[p] = rp ? *(const float4*)(rp + (s & 7)*4) : make_float4(0.f,0.f,0.f,0.f);
        }
        char* bc = sm;
        #pragma unroll
        for (int p = 0; p < 4; p++) {
            int s = tid + 256*p;
            int m = s >> 3, kq = s & 7;
            unsigned h0, l0, h1, l1;
            split_pair_f16(av[p].x, av[p].y, h0, l0);
            split_pair_f16(av[p].z, av[p].w, h1, l1);
            unsigned aoff = (unsigned)(m*(A128_STRIDE*2) + kq*8);
            *(uint2*)(bc + AH128 + aoff) = make_uint2(h0, h1);
            *(uint2*)(bc + AL128 + aoff) = make_uint2(l0, l1);
        }
        CPA_WAIT0();
        __syncthreads();
    }

    for (int c = 0; c < nch; c++) {
        int buf = c & 1;
        bool has = (c + 1 < nch);
        if (has) {
            int kc = (c + 1) << 5;
            unsigned bb = smbase + (unsigned)((buf ^ 1) * BUF128);
            #pragma unroll
            for (int p = 0; p < 2; p++) {
                int s = tid + 256*p;
                CPA16(bb + BH128 + (s >> 4)*272 + (s & 15)*16,
                      (const char*)(We + (size_t)(kc + (s >> 4))*N + n0 + (s & 15)*8));
            }
            CPA_COMMIT();
            #pragma unroll
            for (int p = 0; p < 4; p++) {
                int s = tid + 256*p;
                const float* rp = rowp[s >> 3];
                av[p] = rp ? *(const float4*)(rp + kc + (s & 7)*4) : make_float4(0.f,0.f,0.f,0.f);
            }
        }
        unsigned bufo = (unsigned)(buf * BUF128);
        #pragma unroll
        for (int ks = 0; ks < 2; ks++) {
            unsigned ah[4][4], al[4][4], bf[2][4];
            unsigned ab = a_base + bufo + ks*32;
            unsigned bb2 = b_base + bufo + ks*16*(B128_STRIDE*2);
            #pragma unroll
            for (int i = 0; i < 4; i++) {
                ldm_x4(ah[i], ab + i*16*(A128_STRIDE*2));
                ldm_x4(al[i], ab + i*16*(A128_STRIDE*2) + (AL128 - AH128));
            }
            #pragma unroll
            for (int jj = 0; jj < 2; jj++) ldm_x4t(bf[jj], bb2 + jj*32);
            #pragma unroll
            for (int i = 0; i < 4; i++)
                #pragma unroll
                for (int j = 0; j < 4; j++) {
                    mma_f16(acc[i][j], ah[i], &bf[j >> 1][(j & 1)*2]);
                    mma_f16(acc[i][j], al[i], &bf[j >> 1][(j & 1)*2]);
                }
        }
        if (has) {
            char* bc = sm + (buf ^ 1) * BUF128;
            #pragma unroll
            for (int p = 0; p < 4; p++) {
                int s = tid + 256*p;
                int m = s >> 3, kq = s & 7;
                unsigned h0, l0, h1, l1;
                split_pair_f16(av[p].x, av[p].y, h0, l0);
                split_pair_f16(av[p].z, av[p].w, h1, l1);
                unsigned aoff = (unsigned)(m*(A128_STRIDE*2) + kq*8);
                *(uint2*)(bc + AH128 + aoff) = make_uint2(h0, h1);
                *(uint2*)(bc + AL128 + aoff) = make_uint2(l0, l1);
            }
            CPA_WAIT0();
        }
        __syncthreads();
    }

    // ---- epilogue: fp16 out ----
    #pragma unroll
    for (int i = 0; i < 4; i++) {
        int r0 = m0 + wm*64 + 16*i + (lane >> 2);
        #pragma unroll
        for (int hf = 0; hf < 2; hf++) {
            int row = r0 + hf*8;
            if (row >= rows) continue;
            __half* orow = outh + ((size_t)e*TOK + row) * N;
            #pragma unroll
            for (int j = 0; j < 4; j++) {
                int col = n0 + wn*32 + 8*j + 2*(lane & 3);
                float v0 = acc[i][j][hf*2 + 0];
                float v1 = acc[i][j][hf*2 + 1];
                v0 += be[col]; v1 += be[col + 1];
                if (relu) { v0 = fmaxf(v0, 0.f); v1 = fmaxf(v1, 0.f); }
                *(unsigned*)(orow + col) = pack_f16(v0, v1);
            }
        }
    }
}

// ================= hgemm_h: fp16 A (single plane) + fp16 W, 32 MMAs/chunk ========
// mode 2: expert A at e*TOK -> fp16 outh at e*TOK (+relu)
// mode 3: expert A at e*TOK -> fp32 scatter by list
// mode 10: plain A (rows=M) -> fp32 C + bias (+resid)
// mode 15: dual launch z: W/bias select, fp32 C slice z*TOK*N (K/V)
#define AH_H  0
#define BH_H  10240
#define BUFH  18944        // A(10240) + B(8704)
#define SMEMH (2*BUFH + 256)

extern "C" __global__ void __launch_bounds__(256, 2)
hgemm_h(const __half* __restrict__ Ah, const __half* __restrict__ W16,
        const float* __restrict__ bias, const float* __restrict__ resid,
        float* __restrict__ C, __half* __restrict__ outh,
        int M, int N, int K, int lda,
        const int* __restrict__ list, const int* __restrict__ cntp,
        int mode, int relu,
        const __half* Wv16b, const float* bvb) {
    extern __shared__ char sm_raw[];
    char* sm = (char*)(((ull)sm_raw + 127) & ~127ULL);

    int z = blockIdx.z;
    int e = (mode == 2 || mode == 3) ? z : 0;
    const __half* Wsrc = W16;
    const float* bsrc = bias;
    if (mode == 15 && z == 1) { Wsrc = Wv16b; bsrc = bvb; }
    int rows = cntp ? cntp[e] : M;
    int m0 = blockIdx.y * 128;
    if (m0 >= rows) return;
    int n0 = blockIdx.x * 128;
    int tid = threadIdx.x;
    int lane = tid & 31, w = tid >> 5;
    int wm = w & 1, wn = w >> 1;

    const __half* Ae = Ah + ((size_t)e*TOK + m0) * lda;
    const __half* We = Wsrc + (size_t)e * K * N;
    const float* be = bsrc + (size_t)e * N;

    unsigned smbase = smem_u32(sm);
    int aq = lane >> 3, ar = lane & 7;
    unsigned a_base = smbase + AH_H +
        (unsigned)(((wm*64 + ar + 8*(aq & 1)) * A128_STRIDE + 8*(aq >> 1)) * 2);
    int bt = lane >> 3;
    int bkrow = (bt & 1)*8 + (lane & 7);
    int bnoff = (bt >> 1)*8;
    unsigned b_base = smbase + BH_H +
        (unsigned)((bkrow * B128_STRIDE + wn*32 + bnoff) * 2);

    float acc[4][4][4];
    #pragma unroll
    for (int i = 0; i < 4; i++)
        #pragma unroll
        for (int j = 0; j < 4; j++)
            #pragma unroll
            for (int q = 0; q < 4; q++) acc[i][j][q] = 0.f;

    int nch = K >> 5;

    #define H_STAGE(kc_, bb_) do { \
        _Pragma("unroll") \
        for (int p = 0; p < 2; p++) { \
            int g = tid + 256*p; \
            CPA16((bb_) + AH_H + (g >> 2)*80 + (g & 3)*16, \
                  (const char*)(Ae + (size_t)(g >> 2)*lda + (kc_) + (g & 3)*8)); \
            CPA16((bb_) + BH_H + (g >> 4)*272 + (g & 15)*16, \
                  (const char*)(We + (size_t)((kc_) + (g >> 4))*N + n0 + (g & 15)*8)); \
        } \
        CPA_COMMIT(); \
    } while (0)

    H_STAGE(0, smbase);
    CPA_WAIT0();
    __syncthreads();

    for (int c = 0; c < nch; c++) {
        int buf = c & 1;
        bool has = (c + 1 < nch);
        if (has) H_STAGE((c + 1) << 5, smbase + (unsigned)((buf ^ 1) * BUFH));

        unsigned bufo = (unsigned)(buf * BUFH);
        #pragma unroll
        for (int ks = 0; ks < 2; ks++) {
            unsigned ah[4][4], bf[2][4];
            unsigned ab = a_base + bufo + ks*32;
            unsigned bb2 = b_base + bufo + ks*16*(B128_STRIDE*2);
            #pragma unroll
            for (int i = 0; i < 4; i++) ldm_x4(ah[i], ab + i*16*(A128_STRIDE*2));
            #pragma unroll
            for (int jj = 0; jj < 2; jj++) ldm_x4t(bf[jj], bb2 + jj*32);
            #pragma unroll
            for (int i = 0; i < 4; i++)
                #pragma unroll
                for (int j = 0; j < 4; j++)
                    mma_f16(acc[i][j], ah[i], &bf[j >> 1][(j & 1)*2]);
        }
        if (has) CPA_WAIT0();
        __syncthreads();
    }
    #undef H_STAGE

    // ---- epilogue ----
    #pragma unroll
    for (int i = 0; i < 4; i++) {
        int r0 = m0 + wm*64 + 16*i + (lane >> 2);
        #pragma unroll
        for (int hf = 0; hf < 2; hf++) {
            int row = r0 + hf*8;
            if (row >= rows) continue;
            float* crow = nullptr;
            __half* orow = nullptr;
            const float* rsd = nullptr;
            if (mode == 3) {
                int ent = list[e*TOK + row];
                crow = C + (size_t)(ent & 1)*TOK*N + (size_t)(ent >> 1)*N;
            } else if (mode == 10) {
                crow = C + (size_t)row * N;
                if (resid) rsd = resid + (size_t)row * N;
            } else if (mode == 15) {
                crow = C + (size_t)z*TOK*N + (size_t)row * N;
            } else {
                orow = outh + ((size_t)e*TOK + row) * N;
            }
            #pragma unroll
            for (int j = 0; j < 4; j++) {
                int col = n0 + wn*32 + 8*j + 2*(lane & 3);
                float v0 = acc[i][j][hf*2 + 0];
                float v1 = acc[i][j][hf*2 + 1];
                v0 += be[col]; v1 += be[col + 1];
                if (rsd) { v0 += rsd[col]; v1 += rsd[col + 1]; }
                if (relu) { v0 = fmaxf(v0, 0.f); v1 = fmaxf(v1, 0.f); }
                if (crow) *(float2*)(crow + col) = make_float2(v0, v1);
                else      *(unsigned*)(orow + col) = pack_f16(v0, v1);
            }
        }
    }
}

// ================= hgemm_wl: BM=32 BN=256 BK=32, split-K=4, fp16 2-pass =========
#define AW_STRIDE 40
#define BW_STRIDE 264
#define AHW 0
#define ALW 2560
#define BHW 5120
#define BUFW 22016          // 5120 + 16896
#define SMEMW (2*BUFW + 256)

extern "C" __global__ void __launch_bounds__(256)
hgemm_wl(const float* __restrict__ A, const float* __restrict__ W,
         float* __restrict__ part) {
    extern __shared__ char sm_raw[];
    char* sm = (char*)(((ull)sm_raw + 127) & ~127ULL);

    int n0 = blockIdx.x * 256;
    int z  = blockIdx.y;
    int tid = threadIdx.x;
    int lane = tid & 31, w = tid >> 5;

    const float* Ab = A + (size_t)z * WLKC;
    const float* Wb = W + (size_t)z * WLKC * NBIG;

    unsigned smbase = smem_u32(sm);
    int aq = lane >> 3, ar = lane & 7;
    unsigned a_base = smbase + AHW +
        (unsigned)(((ar + 8*(aq & 1)) * AW_STRIDE + 8*(aq >> 1)) * 2);
    unsigned b_base = smbase + BHW +
        (unsigned)(((lane & 15) * BW_STRIDE + w*32) * 2);

    float acc[2][4][4];
    #pragma unroll
    for (int i = 0; i < 2; i++)
        #pragma unroll
        for (int j = 0; j < 4; j++)
            #pragma unroll
            for (int q = 0; q < 4; q++) acc[i][j][q] = 0.f;

    const int nch = WLKC >> 5;   // 128
    float4 av1; float4 bv[8];

    {
        int m = tid >> 3, kq = tid & 7;
        av1 = *(const float4*)(Ab + (size_t)m*NBIG + kq*4);
        #pragma unroll
        for (int p = 0; p < 8; p++) {
            int s = tid + 256*p;
            bv[p] = *(const float4*)(Wb + (size_t)(s >> 6)*NBIG + n0 + (s & 63)*4);
        }
        char* bb = sm;
        unsigned h0, l0, h1, l1;
        split_pair_f16(av1.x, av1.y, h0, l0);
        split_pair_f16(av1.z, av1.w, h1, l1);
        unsigned aoff = (unsigned)(m*(AW_STRIDE*2) + kq*8);
        *(uint2*)(bb + AHW + aoff) = make_uint2(h0, h1);
        *(uint2*)(bb + ALW + aoff) = make_uint2(l0, l1);
        #pragma unroll
        for (int p = 0; p < 8; p++) {
            int s = tid + 256*p;
            int n4 = s & 63, kk = s >> 6;
            unsigned bh0 = pack_f16(bv[p].x, bv[p].y);
            unsigned bh1 = pack_f16(bv[p].z, bv[p].w);
            unsigned boff = (unsigned)(kk*(BW_STRIDE*2) + n4*8);
            *(uint2*)(bb + BHW + boff) = make_uint2(bh0, bh1);
        }
    }
    __syncthreads();

    for (int c = 0; c < nch; c++) {
        int buf = c & 1;
        bool has = (c + 1 < nch);
        if (has) {
            int kc = (c + 1) << 5;
            int m = tid >> 3, kq = tid & 7;
            av1 = *(const float4*)(Ab + (size_t)m*NBIG + kc + kq*4);
            #pragma unroll
            for (int p = 0; p < 8; p++) {
                int s = tid + 256*p;
                bv[p] = *(const float4*)(Wb + (size_t)(kc + (s >> 6))*NBIG + n0 + (s & 63)*4);
            }
        }
        unsigned bufo = (unsigned)(buf * BUFW);
        #pragma unroll
        for (int ks = 0; ks < 2; ks++) {
            unsigned ah[2][4], al[2][4], bh[4][2];
            unsigned ab = a_base + bufo + ks*32;
            unsigned bb2 = b_base + bufo + ks*16*(BW_STRIDE*2);
            #pragma unroll
            for (int i = 0; i < 2; i++) {
                ldm_x4(ah[i], ab + i*16*(AW_STRIDE*2));
                ldm_x4(al[i], ab + i*16*(AW_STRIDE*2) + (ALW - AHW));
            }
            #pragma unroll
            for (int j = 0; j < 4; j++) ldm_x2t(bh[j], bb2 + j*16);
            #pragma unroll
            for (int i = 0; i < 2; i++)
                #pragma unroll
                for (int j = 0; j < 4; j++) {
                    mma_f16(acc[i][j], ah[i], bh[j]);
                    mma_f16(acc[i][j], al[i], bh[j]);
                }
        }
        if (has) {
            char* bb = sm + (buf ^ 1) * BUFW;
            int m = tid >> 3, kq = tid & 7;
            unsigned h0, l0, h1, l1;
            split_pair_f16(av1.x, av1.y, h0, l0);
            split_pair_f16(av1.z, av1.w, h1, l1);
            unsigned aoff = (unsigned)(m*(AW_STRIDE*2) + kq*8);
            *(uint2*)(bb + AHW + aoff) = make_uint2(h0, h1);
            *(uint2*)(bb + ALW + aoff) = make_uint2(l0, l1);
            #pragma unroll
            for (int p = 0; p < 8; p++) {
                int s = tid + 256*p;
                int n4 = s & 63, kk = s >> 6;
                unsigned bh0 = pack_f16(bv[p].x, bv[p].y);
                unsigned bh1 = pack_f16(bv[p].z, bv[p].w);
                unsigned boff = (unsigned)(kk*(BW_STRIDE*2) + n4*8);
                *(uint2*)(bb + BHW + boff) = make_uint2(bh0, bh1);
            }
        }
        __syncthreads();
    }

    float* pz = part + (size_t)z * 32 * NBIG;
    #pragma unroll
    for (int i = 0; i < 2; i++) {
        int r0 = 16*i + (lane >> 2);
        #pragma unroll
        for (int hf = 0; hf < 2; hf++) {
            int row = r0 + hf*8;
            float* crow = pz + (size_t)row * NBIG;
            #pragma unroll
            for (int j = 0; j < 4; j++) {
                int col = n0 + w*32 + 8*j + 2*(lane & 3);
                *(float2*)(crow + col) =
                    make_float2(acc[i][j][hf*2 + 0], acc[i][j][hf*2 + 1]);
            }
        }
    }
}

// ---------------- weight conversion (vectorized) ----------------
__global__ void cvt_moe_w(const float* __restrict__ W1, const float* __restrict__ Ws,
                          const float* __restrict__ W2, __half* __restrict__ o1,
                          __half* __restrict__ os, __half* __restrict__ o2) {
    size_t i = ((size_t)blockIdx.x * 256 + threadIdx.x) * 4;
    const size_t n1 = (size_t)NEXP*DMODEL*FEXP;
    const size_t ns = (size_t)NEXP*FEXP*FEXP;
    const float* s; __half* d; size_t j;
    if (i < n1)            { s = W1; d = o1; j = i; }
    else if (i < n1 + ns)  { s = Ws; d = os; j = i - n1; }
    else                   { s = W2; d = o2; j = i - n1 - ns; }
    float4 v = *(const float4*)(s + j);
    *(__half2*)(d + j)     = __floats2half2_rn(v.x, v.y);
    *(__half2*)(d + j + 2) = __floats2half2_rn(v.z, v.w);
}
__global__ void cvt_qkvo_w(const float* __restrict__ Wq, const float* __restrict__ Wk,
                           const float* __restrict__ Wv, const float* __restrict__ Wo,
                           __half* __restrict__ oq, __half* __restrict__ ok,
                           __half* __restrict__ ov, __half* __restrict__ oo) {
    size_t i = ((size_t)blockIdx.x * 256 + threadIdx.x) * 4;
    int seg = (int)(i >> 16);
    size_t j = i & 65535;
    const float* s = (seg == 0) ? Wq : (seg == 1) ? Wk : (seg == 2) ? Wv : Wo;
    __half* d = (seg == 0) ? oq : (seg == 1) ? ok : (seg == 2) ? ov : oo;
    float4 v = *(const float4*)(s + j);
    *(__half2*)(d + j)     = __floats2half2_rn(v.x, v.y);
    *(__half2*)(d + j + 2) = __floats2half2_rn(v.z, v.w);
}

// ---------------- rmsnorm: 1 warp per row, 8 rows/block; fp32 + fp16 out --------
__global__ void rmsnorm_kernel(const float* __restrict__ in, const float* __restrict__ w,
                               float* __restrict__ out, __half* __restrict__ outh) {
    int row = blockIdx.x * 8 + (threadIdx.x >> 5);
    int lane = threadIdx.x & 31;
    const float* ip = in + (size_t)row * DMODEL;
    float4 v0 = *(const float4*)(ip + lane*4);
    float4 v1 = *(const float4*)(ip + 128 + lane*4);
    float ss = v0.x*v0.x + v0.y*v0.y + v0.z*v0.z + v0.w*v0.w
             + v1.x*v1.x + v1.y*v1.y + v1.z*v1.z + v1.w*v1.w;
    #pragma unroll
    for (int o = 16; o > 0; o >>= 1) ss += __shfl_xor_sync(0xffffffffu, ss, o);
    float sc = rsqrtf(ss * (1.0f/256.0f) + 1e-5f);
    float4 w0 = *(const float4*)(w + lane*4);
    float4 w1 = *(const float4*)(w + 128 + lane*4);
    float4 r0 = make_float4(v0.x*sc*w0.x, v0.y*sc*w0.y, v0.z*sc*w0.z, v0.w*sc*w0.w);
    float4 r1 = make_float4(v1.x*sc*w1.x, v1.y*sc*w1.y, v1.z*sc*w1.z, v1.w*sc*w1.w);
    float* op = out + (size_t)row * DMODEL;
    *(float4*)(op + lane*4) = r0;
    *(float4*)(op + 128 + lane*4) = r1;
    if (outh) {
        __half* oh = outh + (size_t)row * DMODEL;
        *(uint2*)(oh + lane*4) = make_uint2(pack_f16(r0.x, r0.y), pack_f16(r0.z, r0.w));
        *(uint2*)(oh + 128 + lane*4) = make_uint2(pack_f16(r1.x, r1.y), pack_f16(r1.z, r1.w));
    }
}

// ---------------- Wl split-K reduce -> fp16 lat ----------------
__global__ void wl_reduce(const float* __restrict__ part, const float* __restrict__ bl,
                          __half* __restrict__ lath) {
    int i = (blockIdx.x * 256 + threadIdx.x) * 2;
    float s0 = bl[i & (NBIG-1)];
    float s1 = bl[(i+1) & (NBIG-1)];
    #pragma unroll
    for (int p = 0; p < WLSPLIT; p++) {
        s0 += part[(size_t)p*32*NBIG + i];
        s1 += part[(size_t)p*32*NBIG + i + 1];
    }
    *(unsigned*)(lath + i) = pack_f16(s0, s1);
}

// ---------------- attention (fp32 qkv in, fp16 ao out) ----------------
__global__ void attn_kernel(const float* __restrict__ q, const float* __restrict__ k,
                            const float* __restrict__ v, __half* __restrict__ aoh) {
    int bh = blockIdx.x;
    int b = bh >> 3, h = bh & 7;
    int s = threadIdx.x;
    __shared__ float ks[64][32];
    __shared__ float vs[64][32];
    for (int idx = s; idx < 2048; idx += 64) {
        int l = idx >> 5, d = idx & 31;
        size_t src = (size_t)(b*64 + l)*DMODEL + h*32 + d;
        ks[l][d] = k[src];
        vs[l][d] = v[src];
    }
    __syncthreads();

    float qr[32];
    const float* qp = q + (size_t)(b*64 + s)*DMODEL + h*32;
    #pragma unroll
    for (int d = 0; d < 32; d++) qr[d] = qp[d];

    // RoPE (bug-faithful: imaginary part uses the updated real part)
    #pragma unroll
    for (int i = 0; i < 16; i++) {
        float fr = powf(10000.0f, -(float)i / 16.0f);
        float ang = (float)s * fr;
        float c = cosf(ang), sn = sinf(ang);
        float X = qr[2*i], Y = qr[2*i + 1];
        float nX = X*c - Y*sn;
        float nY = nX*sn + Y*c;
        qr[2*i] = nX; qr[2*i + 1] = nY;
    }

    const float scale = 0.1767766952966369f;
    float sc[64];
    float mx = -1e30f;
    #pragma unroll
    for (int l = 0; l < 64; l++) {
        float p = 0.f;
        #pragma unroll
        for (int d = 0; d < 32; d++) p += qr[d] * ks[l][d];
        p *= scale;
        sc[l] = p;
        mx = fmaxf(mx, p);
    }
    float se = 0.f;
    #pragma unroll
    for (int l = 0; l < 64; l++) { sc[l] = __expf(sc[l] - mx); se += sc[l]; }
    float inv = 1.0f / se;

    __half* op = aoh + (size_t)(b*64 + s)*DMODEL + h*32;
    #pragma unroll
    for (int d = 0; d < 32; d++) {
        float a = 0.f;
        #pragma unroll
        for (int l = 0; l < 64; l++) a += sc[l] * vs[l][d];
        op[d] = __float2half_rn(a * inv);
    }
}

// ---------------- fused rmsnorm2 + router ----------------
__global__ void zero_cnt_kernel(int* cnt) { if (threadIdx.x < NEXP) cnt[threadIdx.x] = 0; }

__global__ void rms_route_kernel(const float* __restrict__ x2, const float* __restrict__ w,
                                 const float* __restrict__ rw, const float* __restrict__ rb,
                                 float* __restrict__ y2, float* __restrict__ topv,
                                 int* __restrict__ cnt, int* __restrict__ list) {
    int tok = blockIdx.x, lane = threadIdx.x;   // 32 threads
    float xv[8];
    #pragma unroll
    for (int j = 0; j < 8; j++) xv[j] = x2[(size_t)tok*DMODEL + j*32 + lane];
    float ss = 0.f;
    #pragma unroll
    for (int j = 0; j < 8; j++) ss += xv[j]*xv[j];
    #pragma unroll
    for (int o = 16; o > 0; o >>= 1) ss += __shfl_xor_sync(0xffffffffu, ss, o);
    float sc = rsqrtf(ss * (1.0f/256.0f) + 1e-5f);
    #pragma unroll
    for (int j = 0; j < 8; j++) {
        xv[j] = xv[j] * sc * w[j*32 + lane];
        y2[(size_t)tok*DMODEL + j*32 + lane] = xv[j];
    }
    float lg[8];
    #pragma unroll
    for (int e = 0; e < 8; e++) {
        float p = 0.f;
        #pragma unroll
        for (int j = 0; j < 8; j++) p += xv[j] * rw[(j*32 + lane)*NEXP + e];
        #pragma unroll
        for (int o = 16; o > 0; o >>= 1) p += __shfl_xor_sync(0xffffffffu, p, o);
        lg[e] = p;
    }
    if (lane == 0) {
        float mx = -1e30f;
        #pragma unroll
        for (int e = 0; e < 8; e++) { lg[e] += rb[e]; mx = fmaxf(mx, lg[e]); }
        float se = 0.f, pr[8];
        #pragma unroll
        for (int e = 0; e < 8; e++) { pr[e] = __expf(lg[e] - mx); se += pr[e]; }
        float inv = 1.0f / se;
        #pragma unroll
        for (int e = 0; e < 8; e++) pr[e] *= inv;
        int b0 = 0; float v0 = -1.f;
        #pragma unroll
        for (int e = 0; e < 8; e++) if (pr[e] > v0) { v0 = pr[e]; b0 = e; }
        int b1 = -1; float v1 = -1.f;
        #pragma unroll
        for (int e = 0; e < 8; e++) if (e != b0 && pr[e] > v1) { v1 = pr[e]; b1 = e; }
        topv[tok*2 + 0] = v0;
        topv[tok*2 + 1] = v1;
        int p0 = atomicAdd(&cnt[b0], 1); list[b0*TOK + p0] = tok*2;
        int p1 = atomicAdd(&cnt[b1], 1); list[b1*TOK + p1] = tok*2 + 1;
    }
}

// ---------------- combine ----------------
__global__ void combine_kernel(const float* __restrict__ x2, const float* __restrict__ topv,
                               const float* __restrict__ eo, float* __restrict__ out) {
    int tok = blockIdx.x, d = threadIdx.x;
    size_t i = (size_t)tok*DMODEL + d;
    out[i] = x2[i] + topv[tok*2] * eo[i] + topv[tok*2 + 1] * eo[(size_t)TOK*DMODEL + i];
}

// ---------------- host ----------------
extern "C" void kernel_launch(void* const* d_in, const int* in_sizes, int n_in,
                              void* d_out, int out_size) {
    const float* x   = (const float*)d_in[0];
    const float* r1w = (const float*)d_in[1];
    const float* Wl  = (const float*)d_in[2];
    const float* bl  = (const float*)d_in[3];
    const float* Wq  = (const float*)d_in[4];
    const float* bq  = (const float*)d_in[5];
    const float* Wk  = (const float*)d_in[6];
    const float* bk  = (const float*)d_in[7];
    const float* Wv  = (const float*)d_in[8];
    const float* bv  = (const float*)d_in[9];
    const float* Wo  = (const float*)d_in[10];
    const float* bo  = (const float*)d_in[11];
    const float* r2w = (const float*)d_in[12];
    const float* rw  = (const float*)d_in[13];
    const float* rb  = (const float*)d_in[14];
    const float* W1  = (const float*)d_in[15];
    const float* b1  = (const float*)d_in[16];
    const float* Wsx = (const float*)d_in[17];
    const float* bs  = (const float*)d_in[18];
    const float* W2  = (const float*)d_in[19];
    const float* b2  = (const float*)d_in[20];

    float *y1, *part, *qkv, *x2, *y2, *topv, *eo;
    __half *y1h, *lath, *aoh, *h1x, *h2x, *w116, *ws16, *w216, *wq16, *wk16, *wv16, *wo16;
    int *cnt, *list;
    cudaGetSymbolAddress((void**)&y1,   g_y1);
    cudaGetSymbolAddress((void**)&y1h,  g_y1h);
    cudaGetSymbolAddress((void**)&part, g_part);
    cudaGetSymbolAddress((void**)&lath, g_lath);
    cudaGetSymbolAddress((void**)&qkv,  g_qkv);
    cudaGetSymbolAddress((void**)&aoh,  g_aoh);
    cudaGetSymbolAddress((void**)&x2,   g_x2);
    cudaGetSymbolAddress((void**)&y2,   g_y2);
    cudaGetSymbolAddress((void**)&topv, g_topv);
    cudaGetSymbolAddress((void**)&cnt,  g_cnt);
    cudaGetSymbolAddress((void**)&list, g_list);
    cudaGetSymbolAddress((void**)&eo,   g_eo);
    cudaGetSymbolAddress((void**)&h1x,  g_h1x);
    cudaGetSymbolAddress((void**)&h2x,  g_h2x);
    cudaGetSymbolAddress((void**)&w116, g_w116);
    cudaGetSymbolAddress((void**)&ws16, g_ws16);
    cudaGetSymbolAddress((void**)&w216, g_w216);
    cudaGetSymbolAddress((void**)&wq16, g_wq16);
    cudaGetSymbolAddress((void**)&wk16, g_wk16);
    cudaGetSymbolAddress((void**)&wv16, g_wv16);
    cudaGetSymbolAddress((void**)&wo16, g_wo16);

    static int inited = 0;
    static cudaStream_t s1, s2;
    static cudaEvent_t evFork, evCvt, evRms1, evQ;
    if (!inited) {
        cudaFuncSetAttribute(hgemm,    cudaFuncAttributeMaxDynamicSharedMemorySize, SMEM128);
        cudaFuncSetAttribute(hgemm_h,  cudaFuncAttributeMaxDynamicSharedMemorySize, SMEMH);
        cudaFuncSetAttribute(hgemm_wl, cudaFuncAttributeMaxDynamicSharedMemorySize, SMEMW);
        cudaStreamCreateWithFlags(&s1, cudaStreamNonBlocking);
        cudaStreamCreateWithFlags(&s2, cudaStreamNonBlocking);
        cudaEventCreateWithFlags(&evFork, cudaEventDisableTiming);
        cudaEventCreateWithFlags(&evCvt,  cudaEventDisableTiming);
        cudaEventCreateWithFlags(&evRms1, cudaEventDisableTiming);
        cudaEventCreateWithFlags(&evQ,    cudaEventDisableTiming);
        inited = 1;
    }

    // ---- side stream s1: weight cvt + cnt zero (off critical path) ----
    cudaEventRecord(evFork, 0);
    cudaStreamWaitEvent(s1, evFork, 0);
    cvt_qkvo_w<<<256, 256, 0, s1>>>(Wq, Wk, Wv, Wo, wq16, wk16, wv16, wo16);
    cvt_moe_w<<<12288, 256, 0, s1>>>(W1, Wsx, W2, w116, ws16, w216);
    zero_cnt_kernel<<<1, 32, 0, s1>>>(cnt);
    cudaEventRecord(evCvt, s1);

    // ---- main chain ----
    rmsnorm_kernel<<<TOK/8, 256>>>(x, r1w, y1, y1h);
    cudaEventRecord(evRms1, 0);

    // ---- s2: Q projection (fp16 A) overlapping Wl ----
    cudaStreamWaitEvent(s2, evRms1, 0);
    cudaStreamWaitEvent(s2, evCvt, 0);
    hgemm_h<<<dim3(2, 16, 1), 256, SMEMH, s2>>>(y1h, wq16, bq, nullptr, qkv, nullptr,
        TOK, DMODEL, DMODEL, DMODEL, nullptr, nullptr, 10, 0, nullptr, nullptr);
    cudaEventRecord(evQ, s2);

    hgemm_wl<<<dim3(64, WLSPLIT), 256, SMEMW>>>(y1, Wl, part);
    wl_reduce<<<TOK/2, 256>>>(part, bl, lath);

    // K/V: mode 15, z=0 -> K(lath,wk16,bk), z=1 -> V(lath,wv16,bv); C = qkv+TOK*D
    cudaStreamWaitEvent(0, evCvt, 0);
    hgemm_h<<<dim3(2, 16, 2), 256, SMEMH>>>(lath, wk16, bk, nullptr,
        qkv + (size_t)TOK*DMODEL, nullptr,
        TOK, DMODEL, DMODEL, DMODEL, nullptr, nullptr, 15, 0, wv16, bv);

    cudaStreamWaitEvent(0, evQ, 0);
    attn_kernel<<<256, 64>>>(qkv, qkv + (size_t)TOK*DMODEL, qkv + 2*(size_t)TOK*DMODEL, aoh);
    hgemm_h<<<dim3(2, 16, 1), 256, SMEMH>>>(aoh, wo16, bo, x, x2, nullptr,
        TOK, DMODEL, DMODEL, DMODEL, nullptr, nullptr, 10, 0, nullptr, nullptr);

    // --- MoE ---
    rms_route_kernel<<<TOK, 32>>>(x2, r2w, rw, rb, y2, topv, cnt, list);
    hgemm<<<dim3(8, 16, NEXP), 256, SMEM128>>>(y2, w116, b1, h1x,
        FEXP, DMODEL, DMODEL, list, cnt, 0);
    hgemm_h<<<dim3(8, 16, NEXP), 256, SMEMH>>>(h1x, ws16, bs, nullptr, nullptr, h2x,
        0, FEXP, FEXP, FEXP, list, cnt, 2, 1, nullptr, nullptr);
    hgemm_h<<<dim3(2, 16, NEXP), 256, SMEMH>>>(h2x, w216, b2, nullptr, eo, nullptr,
        0, DMODEL, FEXP, FEXP, list, cnt, 3, 0, nullptr, nullptr);
    combine_kernel<<<TOK, 256>>>(x2, topv, eo, (float*)d_out);
}